// round 8
// baseline (speedup 1.0000x reference)
#include <cuda_runtime.h>
#include <cuda_fp16.h>
#include <cstdint>

#define D_MODEL 1024
#define N_HEADS 16
#define D_K     64
#define SEQ     2048
#define BSZ     2
#define M_TOK   (BSZ * SEQ)   // 4096 tokens

// ---------------------------------------------------------------------------
// fp16 arena (device global: allocation-free rule). 64M halves = 128 MB.
// ---------------------------------------------------------------------------
#define MEG (1048576ULL)
__device__ __half g_hf[64 * MEG];

static const size_t OFF_IQH = 0,        OFF_IQL = 4 * MEG;
static const size_t OFF_IKH = 8 * MEG,  OFF_IKL = 12 * MEG;
static const size_t OFF_IVH = 16 * MEG, OFF_IVL = 20 * MEG;
static const size_t OFF_WQH = 24 * MEG, OFF_WQL = 25 * MEG;
static const size_t OFF_WKH = 26 * MEG, OFF_WKL = 27 * MEG;
static const size_t OFF_WVH = 28 * MEG, OFF_WVL = 29 * MEG;
static const size_t OFF_WOH = 30 * MEG, OFF_WOL = 31 * MEG;
static const size_t OFF_PQH = 32 * MEG, OFF_PQL = 36 * MEG;
static const size_t OFF_PKH = 40 * MEG, OFF_PKL = 44 * MEG;
static const size_t OFF_PVH = 48 * MEG, OFF_PVL = 52 * MEG;
static const size_t OFF_OH = 56 * MEG,  OFF_OL = 60 * MEG;

// ---------------------------------------------------------------------------
// PTX wrappers (baseline PTX — compiles at compute_103)
// ---------------------------------------------------------------------------
__device__ __forceinline__ uint32_t smem_u32(const void* p) {
    uint32_t a;
    asm("{ .reg .u64 t; cvta.to.shared.u64 t, %1; cvt.u32.u64 %0, t; }"
        : "=r"(a) : "l"(p));
    return a;
}
__device__ __forceinline__ void ldsm_x4(uint32_t* r, uint32_t addr) {
    asm volatile("ldmatrix.sync.aligned.m8n8.x4.shared.b16 {%0,%1,%2,%3}, [%4];"
                 : "=r"(r[0]), "=r"(r[1]), "=r"(r[2]), "=r"(r[3]) : "r"(addr));
}
__device__ __forceinline__ void ldsm_x2(uint32_t* r, uint32_t addr) {
    asm volatile("ldmatrix.sync.aligned.m8n8.x2.shared.b16 {%0,%1}, [%2];"
                 : "=r"(r[0]), "=r"(r[1]) : "r"(addr));
}
__device__ __forceinline__ void ldsm_x2_t(uint32_t* r, uint32_t addr) {
    asm volatile("ldmatrix.sync.aligned.m8n8.x2.trans.shared.b16 {%0,%1}, [%2];"
                 : "=r"(r[0]), "=r"(r[1]) : "r"(addr));
}
__device__ __forceinline__ void mma16816(float* d, const uint32_t* a, const uint32_t* b) {
    asm volatile(
        "mma.sync.aligned.m16n8k16.row.col.f32.f16.f16.f32 "
        "{%0,%1,%2,%3}, {%4,%5,%6,%7}, {%8,%9}, {%0,%1,%2,%3};"
        : "+f"(d[0]), "+f"(d[1]), "+f"(d[2]), "+f"(d[3])
        : "r"(a[0]), "r"(a[1]), "r"(a[2]), "r"(a[3]), "r"(b[0]), "r"(b[1]));
}
__device__ __forceinline__ void cp16(uint32_t saddr, const void* g) {
    asm volatile("cp.async.cg.shared.global [%0], [%1], 16;"
                 :: "r"(saddr), "l"(g));
}
#define CP_COMMIT() asm volatile("cp.async.commit_group;" ::: "memory")
#define CP_WAIT0()  asm volatile("cp.async.wait_group 0;" ::: "memory")

// ---------------------------------------------------------------------------
// Fused split: all 7 tensors in ONE launch.
// ---------------------------------------------------------------------------
struct SplitArgs {
    const float* src[7];
    __half* hi[7];
    __half* lo[7];
};

__global__ __launch_bounds__(256)
void split_all(SplitArgs a)
{
    int blk = blockIdx.x;
    int seg, rel;
    if (blk < 12288) { seg = blk >> 12; rel = blk & 4095; }
    else             { seg = 3 + ((blk - 12288) >> 10); rel = (blk - 12288) & 1023; }
    int i = rel * 256 + threadIdx.x;

    float4 v = ((const float4*)a.src[seg])[i];
    __half h0 = __float2half_rn(v.x), h1 = __float2half_rn(v.y);
    __half h2 = __float2half_rn(v.z), h3 = __float2half_rn(v.w);
    __half2 ph0; ph0.x = h0; ph0.y = h1;
    __half2 ph1; ph1.x = h2; ph1.y = h3;
    __half2 pl0; pl0.x = __float2half_rn(v.x - __half2float(h0));
    pl0.y = __float2half_rn(v.y - __half2float(h1));
    __half2 pl1; pl1.x = __float2half_rn(v.z - __half2float(h2));
    pl1.y = __float2half_rn(v.w - __half2float(h3));
    ((__half2*)a.hi[seg])[i * 2 + 0] = ph0;
    ((__half2*)a.hi[seg])[i * 2 + 1] = ph1;
    ((__half2*)a.lo[seg])[i * 2 + 0] = pl0;
    ((__half2*)a.lo[seg])[i * 2 + 1] = pl1;
}

// ---------------------------------------------------------------------------
// Tensor-core split-fp16 GEMM core.
// CTA tile 128(M) x 256(N), BK=32, 256 threads, warp grid 2x4, warp tile 64x64.
// 2-stage cp.async pipeline, 1 sync/iter.
// ---------------------------------------------------------------------------
#define SP 40                        // smem row stride in halves (80B = 5x16B)
#define A_TSZB (128 * SP * 2)        // 10240
#define B_TSZB (256 * SP * 2)        // 20480
#define STGB (2 * A_TSZB + 2 * B_TSZB)  // 61440
#define GSMEM (2 * STGB)             // 122880

struct GemmOne {
    const __half* Ah; const __half* Al;
    const __half* Bh; const __half* Bl;
    const float* bias;
    __half* Ch; __half* Cl;      // MODE 1 outputs
    float* C;                    // MODE 0 output
    float scale;
};
struct GemmQKV { GemmOne g[3]; };

template<int MODE>
__device__ __forceinline__ void gemm_core(const GemmOne& P, int bm, int bn)
{
    extern __shared__ __align__(16) char dsm[];
    const uint32_t base = smem_u32(dsm);
    const int tid  = threadIdx.x;
    const int wid  = tid >> 5;
    const int lane = tid & 31;
    const int wm = (wid >> 2) * 64;     // 2 warp rows
    const int wn = (wid & 3) * 64;      // 4 warp cols

    float acc[4][8][4];
#pragma unroll
    for (int i = 0; i < 4; i++)
#pragma unroll
        for (int j = 0; j < 8; j++)
#pragma unroll
            for (int r = 0; r < 4; r++) acc[i][j][r] = 0.f;

    const int arow = lane & 15;
    const int acol = (lane >> 4) * 8;
    const int brow = lane & 7;
    const int bcol = ((lane & 15) >> 3) * 8;

    // stage layout: [Ah | Al | Bh | Bl]
    auto load_stage = [&](int stg, int k0) {
        uint32_t sb = base + stg * STGB;
        // A tiles: 128 rows x 4 chunks = 512 chunks each
#pragma unroll
        for (int j = 0; j < 2; j++) {
            int c    = tid + j * 256;
            int row  = c >> 2;
            int kcol = (c & 3) * 8;
            size_t ga = (size_t)(bm + row) * D_MODEL + k0 + kcol;
            uint32_t so = (uint32_t)(row * SP + kcol) * 2;
            cp16(sb + so, &P.Ah[ga]);
            cp16(sb + A_TSZB + so, &P.Al[ga]);
        }
        // B tiles: 256 rows x 4 chunks = 1024 chunks each
#pragma unroll
        for (int j = 0; j < 4; j++) {
            int c    = tid + j * 256;
            int row  = c >> 2;
            int kcol = (c & 3) * 8;
            size_t gb = (size_t)(bn + row) * D_MODEL + k0 + kcol;
            uint32_t so = (uint32_t)(row * SP + kcol) * 2;
            cp16(sb + 2 * A_TSZB + so, &P.Bh[gb]);
            cp16(sb + 2 * A_TSZB + B_TSZB + so, &P.Bl[gb]);
        }
    };

    load_stage(0, 0);
    CP_COMMIT();

    for (int kc = 0; kc < 32; kc++) {
        const int cur = kc & 1;
        CP_WAIT0();
        __syncthreads();
        if (kc < 31) {
            load_stage(cur ^ 1, (kc + 1) * 32);
            CP_COMMIT();
        }

        const uint32_t uAh = base + cur * STGB;
        const uint32_t uAl = uAh + A_TSZB;
        const uint32_t uBh = uAh + 2 * A_TSZB;
        const uint32_t uBl = uBh + B_TSZB;

#pragma unroll
        for (int ks = 0; ks < 2; ks++) {
            uint32_t ah[4][4];
            uint32_t bb[8][2];
#pragma unroll
            for (int mt = 0; mt < 4; mt++) {
                uint32_t off = ((wm + mt * 16 + arow) * SP + ks * 16 + acol) * 2;
                ldsm_x4(ah[mt], uAh + off);
            }
#pragma unroll
            for (int nt = 0; nt < 8; nt++) {
                uint32_t off = ((wn + nt * 8 + brow) * SP + ks * 16 + bcol) * 2;
                ldsm_x2(bb[nt], uBh + off);
            }
#pragma unroll
            for (int mt = 0; mt < 4; mt++)
#pragma unroll
                for (int nt = 0; nt < 8; nt++)
                    mma16816(acc[mt][nt], ah[mt], bb[nt]);

            {
                uint32_t al[4][4];
#pragma unroll
                for (int mt = 0; mt < 4; mt++) {
                    uint32_t off = ((wm + mt * 16 + arow) * SP + ks * 16 + acol) * 2;
                    ldsm_x4(al[mt], uAl + off);
                }
#pragma unroll
                for (int mt = 0; mt < 4; mt++)
#pragma unroll
                    for (int nt = 0; nt < 8; nt++)
                        mma16816(acc[mt][nt], al[mt], bb[nt]);
            }

#pragma unroll
            for (int nt = 0; nt < 8; nt++) {
                uint32_t off = ((wn + nt * 8 + brow) * SP + ks * 16 + bcol) * 2;
                ldsm_x2(bb[nt], uBl + off);
            }
#pragma unroll
            for (int mt = 0; mt < 4; mt++)
#pragma unroll
                for (int nt = 0; nt < 8; nt++)
                    mma16816(acc[mt][nt], ah[mt], bb[nt]);
        }
    }

#pragma unroll
    for (int mt = 0; mt < 4; mt++) {
#pragma unroll
        for (int half = 0; half < 2; half++) {
            int m = bm + wm + mt * 16 + (lane >> 2) + half * 8;
            int b = m >> 11, s = m & 2047;
#pragma unroll
            for (int nt = 0; nt < 8; nt++) {
                int n = bn + wn + nt * 8 + 2 * (lane & 3);
                float vx = (acc[mt][nt][half * 2 + 0] + P.bias[n + 0]) * P.scale;
                float vy = (acc[mt][nt][half * 2 + 1] + P.bias[n + 1]) * P.scale;
                if (MODE == 1) {
                    int h = n >> 6, dd = n & 63;
                    size_t co = ((size_t)(b * N_HEADS + h) * SEQ + s) * D_K + dd;
                    __half hx = __float2half_rn(vx), hy = __float2half_rn(vy);
                    __half2 hh; hh.x = hx; hh.y = hy;
                    __half2 ll;
                    ll.x = __float2half_rn(vx - __half2float(hx));
                    ll.y = __float2half_rn(vy - __half2float(hy));
                    *(__half2*)&P.Ch[co] = hh;
                    *(__half2*)&P.Cl[co] = ll;
                } else {
                    float2 v; v.x = vx; v.y = vy;
                    *(float2*)&P.C[(size_t)m * D_MODEL + n] = v;
                }
            }
        }
    }
}

__global__ __launch_bounds__(256)
void gemm_qkv(GemmQKV P)
{
    gemm_core<1>(P.g[blockIdx.z], blockIdx.y * 128, blockIdx.x * 256);
}

__global__ __launch_bounds__(256)
void gemm_o(GemmOne P)
{
    gemm_core<0>(P, blockIdx.y * 128, blockIdx.x * 256);
}

// ---------------------------------------------------------------------------
// Flash attention, mma.sync fp16-split.
// 128 threads (4 warps), 32 q-rows per warp (128 per CTA), KV tiles 64.
// Q staged in dedicated smem region, fragments reloaded per ks.
// 2-stage cp.async KV pipeline.
// ---------------------------------------------------------------------------
#define ST 72                        // smem row stride in halves (144B)
#define FTSZB (64 * ST * 2)          // 9216  (one 64-row kv tile)
#define FSTGB (4 * FTSZB)            // 36864 (Kh,Kl,Vh,Vl)
#define QTSZB (128 * ST * 2)         // 18432 (one 128-row q tile)
#define QOFF  (2 * FSTGB)            // Q region after 2 KV stages
#define FSMEM (2 * FSTGB + 2 * QTSZB)  // 110592

__global__ __launch_bounds__(128)
void flash_mma(const __half* __restrict__ Qh, const __half* __restrict__ Ql,
               const __half* __restrict__ Kh, const __half* __restrict__ Kl,
               const __half* __restrict__ Vh, const __half* __restrict__ Vl,
               __half* __restrict__ Oh, __half* __restrict__ Ol)
{
    extern __shared__ __align__(16) char fsm[];
    const uint32_t base = smem_u32(fsm);

    const int bh  = blockIdx.y;
    const int q0  = blockIdx.x * 128;
    const int tid = threadIdx.x;
    const int w   = tid >> 5;
    const int lane = tid & 31;
    const size_t bhoff = (size_t)bh * SEQ * D_K;

    const uint32_t uQh = base + QOFF;
    const uint32_t uQl = uQh + QTSZB;

    // ---- stage Q (128 rows) into dedicated smem region ----
    {
        __half* sQh = (__half*)(fsm + QOFF);
        __half* sQl = (__half*)(fsm + QOFF + QTSZB);
#pragma unroll
        for (int it = 0; it < 8; it++) {
            int idx = tid + it * 128;
            int row = idx >> 3, c8 = (idx & 7) * 8;
            size_t g = bhoff + (size_t)(q0 + row) * D_K + c8;
            *(uint4*)&sQh[row * ST + c8] = *(const uint4*)&Qh[g];
            *(uint4*)&sQl[row * ST + c8] = *(const uint4*)&Ql[g];
        }
    }

    auto load_kv = [&](int stg, int kv0) {
        uint32_t sb = base + stg * FSTGB;
#pragma unroll
        for (int it = 0; it < 4; it++) {
            int idx = tid + it * 128;
            int row = idx >> 3, c8 = (idx & 7) * 8;
            size_t g = bhoff + (size_t)(kv0 + row) * D_K + c8;
            uint32_t so = (uint32_t)(row * ST + c8) * 2;
            cp16(sb + 0 * FTSZB + so, &Kh[g]);
            cp16(sb + 1 * FTSZB + so, &Kl[g]);
            cp16(sb + 2 * FTSZB + so, &Vh[g]);
            cp16(sb + 3 * FTSZB + so, &Vl[g]);
        }
    };

    float o[2][8][4];
#pragma unroll
    for (int mt = 0; mt < 2; mt++)
#pragma unroll
        for (int i = 0; i < 8; i++)
#pragma unroll
            for (int r = 0; r < 4; r++) o[mt][i][r] = 0.f;
    float mA[2] = { -1e30f, -1e30f }, mB[2] = { -1e30f, -1e30f };
    float lA[2] = { 0.f, 0.f },       lB[2] = { 0.f, 0.f };

    load_kv(0, 0);
    CP_COMMIT();
    __syncthreads();   // Q staging visible to all (also covered by pipeline syncs later)

    const int arow = lane & 15;
    const int acol = (lane >> 4) * 8;
    const int brow = lane & 7;
    const int bcol = ((lane & 15) >> 3) * 8;

    for (int t = 0; t < SEQ / 64; t++) {
        const int cur = t & 1;
        CP_WAIT0();
        __syncthreads();
        if (t < SEQ / 64 - 1) {
            load_kv(cur ^ 1, (t + 1) * 64);
            CP_COMMIT();
        }

        const uint32_t uKh = base + cur * FSTGB;
        const uint32_t uKl = uKh + FTSZB;
        const uint32_t uVh = uKh + 2 * FTSZB;
        const uint32_t uVl = uKh + 3 * FTSZB;

        // ---- S = Q . K^T (32q x 64kv per warp) ----
        float s[2][8][4];
#pragma unroll
        for (int mt = 0; mt < 2; mt++)
#pragma unroll
            for (int i = 0; i < 8; i++)
#pragma unroll
                for (int r = 0; r < 4; r++) s[mt][i][r] = 0.f;

#pragma unroll
        for (int ks = 0; ks < 4; ks++) {
            uint32_t qf[2][4], kk[8][2];
#pragma unroll
            for (int mt = 0; mt < 2; mt++) {
                uint32_t off = ((w * 32 + mt * 16 + arow) * ST + ks * 16 + acol) * 2;
                ldsm_x4(qf[mt], uQh + off);
            }
#pragma unroll
            for (int nt = 0; nt < 8; nt++) {
                uint32_t off = ((nt * 8 + brow) * ST + ks * 16 + bcol) * 2;
                ldsm_x2(kk[nt], uKh + off);
            }
#pragma unroll
            for (int mt = 0; mt < 2; mt++)
#pragma unroll
                for (int nt = 0; nt < 8; nt++)
                    mma16816(s[mt][nt], qf[mt], kk[nt]);

            {
                uint32_t qg[2][4];
#pragma unroll
                for (int mt = 0; mt < 2; mt++) {
                    uint32_t off = ((w * 32 + mt * 16 + arow) * ST + ks * 16 + acol) * 2;
                    ldsm_x4(qg[mt], uQl + off);
                }
#pragma unroll
                for (int mt = 0; mt < 2; mt++)
#pragma unroll
                    for (int nt = 0; nt < 8; nt++)
                        mma16816(s[mt][nt], qg[mt], kk[nt]);
            }

#pragma unroll
            for (int nt = 0; nt < 8; nt++) {
                uint32_t off = ((nt * 8 + brow) * ST + ks * 16 + bcol) * 2;
                ldsm_x2(kk[nt], uKl + off);
            }
#pragma unroll
            for (int mt = 0; mt < 2; mt++)
#pragma unroll
                for (int nt = 0; nt < 8; nt++)
                    mma16816(s[mt][nt], qf[mt], kk[nt]);
        }

        // ---- online softmax (log2 domain), per m-tile ----
        float mnA[2], mnB[2];
#pragma unroll
        for (int mt = 0; mt < 2; mt++) {
            float tA = -1e30f, tB = -1e30f;
#pragma unroll
            for (int nt = 0; nt < 8; nt++) {
                tA = fmaxf(tA, fmaxf(s[mt][nt][0], s[mt][nt][1]));
                tB = fmaxf(tB, fmaxf(s[mt][nt][2], s[mt][nt][3]));
            }
            tA = fmaxf(tA, __shfl_xor_sync(0xffffffff, tA, 1));
            tA = fmaxf(tA, __shfl_xor_sync(0xffffffff, tA, 2));
            tB = fmaxf(tB, __shfl_xor_sync(0xffffffff, tB, 1));
            tB = fmaxf(tB, __shfl_xor_sync(0xffffffff, tB, 2));
            mnA[mt] = fmaxf(mA[mt], tA);
            mnB[mt] = fmaxf(mB[mt], tB);
            float cA = exp2f(mA[mt] - mnA[mt]);
            float cB = exp2f(mB[mt] - mnB[mt]);
            lA[mt] *= cA; lB[mt] *= cB;
#pragma unroll
            for (int nt = 0; nt < 8; nt++) {
                o[mt][nt][0] *= cA; o[mt][nt][1] *= cA;
                o[mt][nt][2] *= cB; o[mt][nt][3] *= cB;
            }
            mA[mt] = mnA[mt]; mB[mt] = mnB[mt];
        }

        // ---- O += P . V : convert P per kv-slice just-in-time ----
#pragma unroll
        for (int ks = 0; ks < 4; ks++) {
            uint32_t aPh[2][4], aPl[2][4];
#pragma unroll
            for (int mt = 0; mt < 2; mt++) {
#pragma unroll
                for (int half16 = 0; half16 < 2; half16++) {
                    int nt = 2 * ks + half16;
                    float p0 = exp2f(s[mt][nt][0] - mnA[mt]);
                    float p1 = exp2f(s[mt][nt][1] - mnA[mt]);
                    float p2 = exp2f(s[mt][nt][2] - mnB[mt]);
                    float p3 = exp2f(s[mt][nt][3] - mnB[mt]);
                    lA[mt] += p0 + p1; lB[mt] += p2 + p3;
                    __half h0 = __float2half_rn(p0), h1 = __float2half_rn(p1);
                    __half h2 = __float2half_rn(p2), h3 = __float2half_rn(p3);
                    __half2 tt;
                    tt.x = h0; tt.y = h1; aPh[mt][half16 * 2 + 0] = *(uint32_t*)&tt;
                    tt.x = h2; tt.y = h3; aPh[mt][half16 * 2 + 1] = *(uint32_t*)&tt;
                    tt.x = __float2half_rn(p0 - __half2float(h0));
                    tt.y = __float2half_rn(p1 - __half2float(h1));
                    aPl[mt][half16 * 2 + 0] = *(uint32_t*)&tt;
                    tt.x = __float2half_rn(p2 - __half2float(h2));
                    tt.y = __float2half_rn(p3 - __half2float(h3));
                    aPl[mt][half16 * 2 + 1] = *(uint32_t*)&tt;
                }
            }
            uint32_t vv[8][2];
#pragma unroll
            for (int ntd = 0; ntd < 8; ntd++) {
                uint32_t off = ((ks * 16 + (lane & 15)) * ST + ntd * 8) * 2;
                ldsm_x2_t(vv[ntd], uVh + off);
            }
#pragma unroll
            for (int mt = 0; mt < 2; mt++)
#pragma unroll
                for (int ntd = 0; ntd < 8; ntd++)
                    mma16816(o[mt][ntd], aPh[mt], vv[ntd]);
#pragma unroll
            for (int mt = 0; mt < 2; mt++)
#pragma unroll
                for (int ntd = 0; ntd < 8; ntd++)
                    mma16816(o[mt][ntd], aPl[mt], vv[ntd]);
#pragma unroll
            for (int ntd = 0; ntd < 8; ntd++) {
                uint32_t off = ((ks * 16 + (lane & 15)) * ST + ntd * 8) * 2;
                ldsm_x2_t(vv[ntd], uVl + off);
            }
#pragma unroll
            for (int mt = 0; mt < 2; mt++)
#pragma unroll
                for (int ntd = 0; ntd < 8; ntd++)
                    mma16816(o[mt][ntd], aPh[mt], vv[ntd]);
        }
    }

    // ---- finalize ----
    const int b = bh >> 4, h = bh & 15;
    const int c2 = 2 * (lane & 3);
#pragma unroll
    for (int mt = 0; mt < 2; mt++) {
        float la = lA[mt], lb = lB[mt];
        la += __shfl_xor_sync(0xffffffff, la, 1);
        la += __shfl_xor_sync(0xffffffff, la, 2);
        lb += __shfl_xor_sync(0xffffffff, lb, 1);
        lb += __shfl_xor_sync(0xffffffff, lb, 2);
        float invA = 1.f / la, invB = 1.f / lb;
        int rowA = q0 + w * 32 + mt * 16 + (lane >> 2);
        int rowB = rowA + 8;
#pragma unroll
        for (int ntd = 0; ntd < 8; ntd++) {
            float v0 = o[mt][ntd][0] * invA, v1 = o[mt][ntd][1] * invA;
            float v2 = o[mt][ntd][2] * invB, v3 = o[mt][ntd][3] * invB;
            size_t offA = (size_t)(b * SEQ + rowA) * D_MODEL + h * D_K + ntd * 8 + c2;
            size_t offB = (size_t)(b * SEQ + rowB) * D_MODEL + h * D_K + ntd * 8 + c2;
            __half h0 = __float2half_rn(v0), h1 = __float2half_rn(v1);
            __half h2 = __float2half_rn(v2), h3 = __float2half_rn(v3);
            __half2 t2;
            t2.x = h0; t2.y = h1; *(__half2*)&Oh[offA] = t2;
            t2.x = __float2half_rn(v0 - __half2float(h0));
            t2.y = __float2half_rn(v1 - __half2float(h1));
            *(__half2*)&Ol[offA] = t2;
            t2.x = h2; t2.y = h3; *(__half2*)&Oh[offB] = t2;
            t2.x = __float2half_rn(v2 - __half2float(h2));
            t2.y = __float2half_rn(v3 - __half2float(h3));
            *(__half2*)&Ol[offB] = t2;
        }
    }
}

// ---------------------------------------------------------------------------
// Launch
// ---------------------------------------------------------------------------
extern "C" void kernel_launch(void* const* d_in, const int* in_sizes, int n_in,
                              void* d_out, int out_size)
{
    const float* q   = (const float*)d_in[0];
    const float* k   = (const float*)d_in[1];
    const float* v   = (const float*)d_in[2];
    const float* W_q = (const float*)d_in[3];
    const float* b_q = (const float*)d_in[4];
    const float* W_k = (const float*)d_in[5];
    const float* b_k = (const float*)d_in[6];
    const float* W_v = (const float*)d_in[7];
    const float* b_v = (const float*)d_in[8];
    const float* W_o = (const float*)d_in[9];
    const float* b_o = (const float*)d_in[10];
    float* out = (float*)d_out;

    __half* hf;
    cudaGetSymbolAddress((void**)&hf, g_hf);

    cudaFuncSetAttribute((void*)gemm_qkv, cudaFuncAttributeMaxDynamicSharedMemorySize, GSMEM);
    cudaFuncSetAttribute((void*)gemm_o,   cudaFuncAttributeMaxDynamicSharedMemorySize, GSMEM);
    cudaFuncSetAttribute((void*)flash_mma, cudaFuncAttributeMaxDynamicSharedMemorySize, FSMEM);

    SplitArgs sa;
    sa.src[0] = q;   sa.hi[0] = hf + OFF_IQH; sa.lo[0] = hf + OFF_IQL;
    sa.src[1] = k;   sa.hi[1] = hf + OFF_IKH; sa.lo[1] = hf + OFF_IKL;
    sa.src[2] = v;   sa.hi[2] = hf + OFF_IVH; sa.lo[2] = hf + OFF_IVL;
    sa.src[3] = W_q; sa.hi[3] = hf + OFF_WQH; sa.lo[3] = hf + OFF_WQL;
    sa.src[4] = W_k; sa.hi[4] = hf + OFF_WKH; sa.lo[4] = hf + OFF_WKL;
    sa.src[5] = W_v; sa.hi[5] = hf + OFF_WVH; sa.lo[5] = hf + OFF_WVL;
    sa.src[6] = W_o; sa.hi[6] = hf + OFF_WOH; sa.lo[6] = hf + OFF_WOL;
    split_all<<<16384, 256>>>(sa);

    const float qscale = 0.125f * 1.4426950408889634f;
    GemmQKV gp;
    gp.g[0] = { hf + OFF_IQH, hf + OFF_IQL, hf + OFF_WQH, hf + OFF_WQL, b_q,
                hf + OFF_PQH, hf + OFF_PQL, nullptr, qscale };
    gp.g[1] = { hf + OFF_IKH, hf + OFF_IKL, hf + OFF_WKH, hf + OFF_WKL, b_k,
                hf + OFF_PKH, hf + OFF_PKL, nullptr, 1.0f };
    gp.g[2] = { hf + OFF_IVH, hf + OFF_IVL, hf + OFF_WVH, hf + OFF_WVL, b_v,
                hf + OFF_PVH, hf + OFF_PVL, nullptr, 1.0f };
    dim3 ggrid(D_MODEL / 256, M_TOK / 128, 3);   // (4, 32, 3)
    gemm_qkv<<<ggrid, 256, GSMEM>>>(gp);

    dim3 agrid(SEQ / 128, BSZ * N_HEADS);        // (16, 32)
    flash_mma<<<agrid, 128, FSMEM>>>(hf + OFF_PQH, hf + OFF_PQL,
                                     hf + OFF_PKH, hf + OFF_PKL,
                                     hf + OFF_PVH, hf + OFF_PVL,
                                     hf + OFF_OH, hf + OFF_OL);

    GemmOne go = { hf + OFF_OH, hf + OFF_OL, hf + OFF_WOH, hf + OFF_WOL, b_o,
                   nullptr, nullptr, out, 1.0f };
    dim3 ogrid(D_MODEL / 256, M_TOK / 128, 1);
    gemm_o<<<ogrid, 256, GSMEM>>>(go);
}

// round 9
// speedup vs baseline: 1.0231x; 1.0231x over previous
#include <cuda_runtime.h>
#include <cuda_fp16.h>
#include <cstdint>

#define D_MODEL 1024
#define N_HEADS 16
#define D_K     64
#define SEQ     2048
#define BSZ     2
#define M_TOK   (BSZ * SEQ)   // 4096 tokens

// ---------------------------------------------------------------------------
// fp16 arena (device global: allocation-free rule). 64M halves = 128 MB.
// ---------------------------------------------------------------------------
#define MEG (1048576ULL)
__device__ __half g_hf[64 * MEG];

static const size_t OFF_IQH = 0,        OFF_IQL = 4 * MEG;
static const size_t OFF_IKH = 8 * MEG,  OFF_IKL = 12 * MEG;
static const size_t OFF_IVH = 16 * MEG, OFF_IVL = 20 * MEG;
static const size_t OFF_WQH = 24 * MEG, OFF_WQL = 25 * MEG;
static const size_t OFF_WKH = 26 * MEG, OFF_WKL = 27 * MEG;
static const size_t OFF_WVH = 28 * MEG, OFF_WVL = 29 * MEG;
static const size_t OFF_WOH = 30 * MEG, OFF_WOL = 31 * MEG;
static const size_t OFF_PQH = 32 * MEG, OFF_PQL = 36 * MEG;
static const size_t OFF_PKH = 40 * MEG, OFF_PKL = 44 * MEG;
static const size_t OFF_PVH = 48 * MEG, OFF_PVL = 52 * MEG;
static const size_t OFF_OH = 56 * MEG,  OFF_OL = 60 * MEG;

// ---------------------------------------------------------------------------
// PTX wrappers (baseline PTX — compiles at compute_103)
// ---------------------------------------------------------------------------
__device__ __forceinline__ uint32_t smem_u32(const void* p) {
    uint32_t a;
    asm("{ .reg .u64 t; cvta.to.shared.u64 t, %1; cvt.u32.u64 %0, t; }"
        : "=r"(a) : "l"(p));
    return a;
}
__device__ __forceinline__ void ldsm_x4(uint32_t* r, uint32_t addr) {
    asm volatile("ldmatrix.sync.aligned.m8n8.x4.shared.b16 {%0,%1,%2,%3}, [%4];"
                 : "=r"(r[0]), "=r"(r[1]), "=r"(r[2]), "=r"(r[3]) : "r"(addr));
}
__device__ __forceinline__ void ldsm_x2(uint32_t* r, uint32_t addr) {
    asm volatile("ldmatrix.sync.aligned.m8n8.x2.shared.b16 {%0,%1}, [%2];"
                 : "=r"(r[0]), "=r"(r[1]) : "r"(addr));
}
__device__ __forceinline__ void ldsm_x2_t(uint32_t* r, uint32_t addr) {
    asm volatile("ldmatrix.sync.aligned.m8n8.x2.trans.shared.b16 {%0,%1}, [%2];"
                 : "=r"(r[0]), "=r"(r[1]) : "r"(addr));
}
__device__ __forceinline__ void mma16816(float* d, const uint32_t* a, const uint32_t* b) {
    asm volatile(
        "mma.sync.aligned.m16n8k16.row.col.f32.f16.f16.f32 "
        "{%0,%1,%2,%3}, {%4,%5,%6,%7}, {%8,%9}, {%0,%1,%2,%3};"
        : "+f"(d[0]), "+f"(d[1]), "+f"(d[2]), "+f"(d[3])
        : "r"(a[0]), "r"(a[1]), "r"(a[2]), "r"(a[3]), "r"(b[0]), "r"(b[1]));
}
__device__ __forceinline__ void cp16(uint32_t saddr, const void* g) {
    asm volatile("cp.async.cg.shared.global [%0], [%1], 16;"
                 :: "r"(saddr), "l"(g));
}
#define CP_COMMIT() asm volatile("cp.async.commit_group;" ::: "memory")
#define CP_WAIT0()  asm volatile("cp.async.wait_group 0;" ::: "memory")

// ---------------------------------------------------------------------------
// Fused split: all 7 tensors in ONE launch.
// ---------------------------------------------------------------------------
struct SplitArgs {
    const float* src[7];
    __half* hi[7];
    __half* lo[7];
};

__global__ __launch_bounds__(256)
void split_all(SplitArgs a)
{
    int blk = blockIdx.x;
    int seg, rel;
    if (blk < 12288) { seg = blk >> 12; rel = blk & 4095; }
    else             { seg = 3 + ((blk - 12288) >> 10); rel = (blk - 12288) & 1023; }
    int i = rel * 256 + threadIdx.x;

    float4 v = ((const float4*)a.src[seg])[i];
    __half h0 = __float2half_rn(v.x), h1 = __float2half_rn(v.y);
    __half h2 = __float2half_rn(v.z), h3 = __float2half_rn(v.w);
    __half2 ph0; ph0.x = h0; ph0.y = h1;
    __half2 ph1; ph1.x = h2; ph1.y = h3;
    __half2 pl0; pl0.x = __float2half_rn(v.x - __half2float(h0));
    pl0.y = __float2half_rn(v.y - __half2float(h1));
    __half2 pl1; pl1.x = __float2half_rn(v.z - __half2float(h2));
    pl1.y = __float2half_rn(v.w - __half2float(h3));
    ((__half2*)a.hi[seg])[i * 2 + 0] = ph0;
    ((__half2*)a.hi[seg])[i * 2 + 1] = ph1;
    ((__half2*)a.lo[seg])[i * 2 + 0] = pl0;
    ((__half2*)a.lo[seg])[i * 2 + 1] = pl1;
}

// ---------------------------------------------------------------------------
// Tensor-core split-fp16 GEMM core.
// CTA 128x128, BK=64 (4 ks-steps/stage), 256 threads, warp tile 64x32.
// 2-stage cp.async smem pipeline + double-buffered register fragments:
// ks+1 LDSMs are issued interleaved with ks MMA batches so each warp keeps
// its SMSP tensor pipe fed (HMMA rt ~8 cyc/SMSP).
// ---------------------------------------------------------------------------
#define GSP 72                       // smem row stride in halves (144B = 9x16B)
#define GT   (128 * GSP * 2)         // bytes per tile (18432)
#define GSTG (4 * GT)                // per stage: Ah,Al,Bh,Bl (73728)
#define GSMEM (2 * GSTG)             // 147456

struct GemmOne {
    const __half* Ah; const __half* Al;
    const __half* Bh; const __half* Bl;
    const float* bias;
    __half* Ch; __half* Cl;      // MODE 1 outputs
    float* C;                    // MODE 0 output
    float scale;
};
struct GemmQKV { GemmOne g[3]; };

template<int MODE>
__device__ __forceinline__ void gemm_core(const GemmOne& P, int bm, int bn)
{
    extern __shared__ __align__(16) char dsm[];
    const uint32_t base = smem_u32(dsm);
    const int tid  = threadIdx.x;
    const int wid  = tid >> 5;
    const int lane = tid & 31;
    const int wm = (wid >> 2) * 64;     // warp grid 2(m) x 4(n), tile 64x32
    const int wn = (wid & 3) * 32;

    float acc[4][4][4];
#pragma unroll
    for (int i = 0; i < 4; i++)
#pragma unroll
        for (int j = 0; j < 4; j++)
#pragma unroll
            for (int r = 0; r < 4; r++) acc[i][j][r] = 0.f;

    const int arow = lane & 15;
    const int acol = (lane >> 4) * 8;
    const int brow = lane & 7;
    const int bcol = ((lane & 15) >> 3) * 8;

    auto load_stage = [&](int stg, int k0) {   // k0 in halves
        uint32_t sb = base + stg * GSTG;
#pragma unroll
        for (int j = 0; j < 4; j++) {
            int c    = tid + j * 256;          // 0..1023
            int row  = c >> 3;
            int kcol = (c & 7) * 8;            // halves
            size_t ga = (size_t)(bm + row) * D_MODEL + k0 + kcol;
            size_t gb = (size_t)(bn + row) * D_MODEL + k0 + kcol;
            uint32_t so = (uint32_t)(row * GSP + kcol) * 2;
            cp16(sb + 0 * GT + so, &P.Ah[ga]);
            cp16(sb + 1 * GT + so, &P.Al[ga]);
            cp16(sb + 2 * GT + so, &P.Bh[gb]);
            cp16(sb + 3 * GT + so, &P.Bl[gb]);
        }
    };

    load_stage(0, 0);
    CP_COMMIT();

    // double-buffered fragments
    uint32_t ah[2][4][4], al[2][4][4], bh[2][4][2], bl[2][4][2];

    for (int kc = 0; kc < 16; kc++) {
        const int cur = kc & 1;
        CP_WAIT0();
        __syncthreads();
        if (kc < 15) {
            load_stage(cur ^ 1, (kc + 1) * 64);
            CP_COMMIT();
        }

        const uint32_t uAh = base + cur * GSTG;
        const uint32_t uAl = uAh + GT;
        const uint32_t uBh = uAh + 2 * GT;
        const uint32_t uBl = uAh + 3 * GT;

        // prologue: fragments for ks=0 into buffer 0
#pragma unroll
        for (int mt = 0; mt < 4; mt++) {
            uint32_t off = ((wm + mt * 16 + arow) * GSP + acol) * 2;
            ldsm_x4(ah[0][mt], uAh + off);
            ldsm_x4(al[0][mt], uAl + off);
        }
#pragma unroll
        for (int nt = 0; nt < 4; nt++) {
            uint32_t off = ((wn + nt * 8 + brow) * GSP + bcol) * 2;
            ldsm_x2(bh[0][nt], uBh + off);
            ldsm_x2(bl[0][nt], uBl + off);
        }

#pragma unroll
        for (int ks = 0; ks < 4; ks++) {
            const int fb = ks & 1;
            const int nb = fb ^ 1;

            // pass 1: Ahi x Bhi, with next-ks A loads interleaved
            if (ks < 3) {
#pragma unroll
                for (int mt = 0; mt < 4; mt++) {
                    uint32_t off = ((wm + mt * 16 + arow) * GSP + (ks + 1) * 16 + acol) * 2;
                    ldsm_x4(ah[nb][mt], uAh + off);
                }
            }
#pragma unroll
            for (int mt = 0; mt < 4; mt++)
#pragma unroll
                for (int nt = 0; nt < 4; nt++)
                    mma16816(acc[mt][nt], ah[fb][mt], bh[fb][nt]);

            // pass 2: Alo x Bhi, with next-ks Al + B loads interleaved
            if (ks < 3) {
#pragma unroll
                for (int mt = 0; mt < 4; mt++) {
                    uint32_t off = ((wm + mt * 16 + arow) * GSP + (ks + 1) * 16 + acol) * 2;
                    ldsm_x4(al[nb][mt], uAl + off);
                }
            }
#pragma unroll
            for (int mt = 0; mt < 4; mt++)
#pragma unroll
                for (int nt = 0; nt < 4; nt++)
                    mma16816(acc[mt][nt], al[fb][mt], bh[fb][nt]);

            // pass 3: Ahi x Blo, with next-ks B loads interleaved
            if (ks < 3) {
#pragma unroll
                for (int nt = 0; nt < 4; nt++) {
                    uint32_t off = ((wn + nt * 8 + brow) * GSP + (ks + 1) * 16 + bcol) * 2;
                    ldsm_x2(bh[nb][nt], uBh + off);
                    ldsm_x2(bl[nb][nt], uBl + off);
                }
            }
#pragma unroll
            for (int mt = 0; mt < 4; mt++)
#pragma unroll
                for (int nt = 0; nt < 4; nt++)
                    mma16816(acc[mt][nt], ah[fb][mt], bl[fb][nt]);
        }
    }

#pragma unroll
    for (int mt = 0; mt < 4; mt++) {
#pragma unroll
        for (int half = 0; half < 2; half++) {
            int m = bm + wm + mt * 16 + (lane >> 2) + half * 8;
            int b = m >> 11, s = m & 2047;
#pragma unroll
            for (int nt = 0; nt < 4; nt++) {
                int n = bn + wn + nt * 8 + 2 * (lane & 3);
                float vx = (acc[mt][nt][half * 2 + 0] + P.bias[n + 0]) * P.scale;
                float vy = (acc[mt][nt][half * 2 + 1] + P.bias[n + 1]) * P.scale;
                if (MODE == 1) {
                    int h = n >> 6, dd = n & 63;
                    size_t co = ((size_t)(b * N_HEADS + h) * SEQ + s) * D_K + dd;
                    __half hx = __float2half_rn(vx), hy = __float2half_rn(vy);
                    __half2 hh; hh.x = hx; hh.y = hy;
                    __half2 ll;
                    ll.x = __float2half_rn(vx - __half2float(hx));
                    ll.y = __float2half_rn(vy - __half2float(hy));
                    *(__half2*)&P.Ch[co] = hh;
                    *(__half2*)&P.Cl[co] = ll;
                } else {
                    float2 v; v.x = vx; v.y = vy;
                    *(float2*)&P.C[(size_t)m * D_MODEL + n] = v;
                }
            }
        }
    }
}

__global__ __launch_bounds__(256)
void gemm_qkv(GemmQKV P)
{
    gemm_core<1>(P.g[blockIdx.z], blockIdx.y * 128, blockIdx.x * 128);
}

__global__ __launch_bounds__(256)
void gemm_o(GemmOne P)
{
    gemm_core<0>(P, blockIdx.y * 128, blockIdx.x * 128);
}

// ---------------------------------------------------------------------------
// Flash attention (R6 version, unchanged): mma.sync fp16-split, 2-stage
// cp.async, 128 threads, 64 q-rows/CTA.
// ---------------------------------------------------------------------------
#define ST 72
#define FTSZB (64 * ST * 2)
#define FSTGB (4 * FTSZB)
#define FSMEM (2 * FSTGB)            // 73728

__global__ __launch_bounds__(128)
void flash_mma(const __half* __restrict__ Qh, const __half* __restrict__ Ql,
               const __half* __restrict__ Kh, const __half* __restrict__ Kl,
               const __half* __restrict__ Vh, const __half* __restrict__ Vl,
               __half* __restrict__ Oh, __half* __restrict__ Ol)
{
    extern __shared__ __align__(16) char fsm[];
    const uint32_t base = smem_u32(fsm);

    const int bh  = blockIdx.y;
    const int q0  = blockIdx.x * 64;
    const int tid = threadIdx.x;
    const int w   = tid >> 5;
    const int lane = tid & 31;
    const size_t bhoff = (size_t)bh * SEQ * D_K;

    // ---- stage Q in buffer 1, extract A-fragments ----
    {
        __half* sQh = (__half*)(fsm + FSTGB);
        __half* sQl = (__half*)(fsm + FSTGB + FTSZB);
#pragma unroll
        for (int it = 0; it < 4; it++) {
            int idx = tid + it * 128;
            int row = idx >> 3, c8 = (idx & 7) * 8;
            size_t g = bhoff + (size_t)(q0 + row) * D_K + c8;
            *(uint4*)&sQh[row * ST + c8] = *(const uint4*)&Qh[g];
            *(uint4*)&sQl[row * ST + c8] = *(const uint4*)&Ql[g];
        }
    }
    __syncthreads();
    uint32_t qh[4][4], ql[4][4];
    {
        const uint32_t uQh = base + FSTGB, uQl = base + FSTGB + FTSZB;
        const int arow = lane & 15, acol = (lane >> 4) * 8;
#pragma unroll
        for (int ks = 0; ks < 4; ks++) {
            uint32_t off = ((w * 16 + arow) * ST + ks * 16 + acol) * 2;
            ldsm_x4(qh[ks], uQh + off);
            ldsm_x4(ql[ks], uQl + off);
        }
    }
    __syncthreads();

    auto load_kv = [&](int stg, int kv0) {
        uint32_t sb = base + stg * FSTGB;
#pragma unroll
        for (int it = 0; it < 4; it++) {
            int idx = tid + it * 128;
            int row = idx >> 3, c8 = (idx & 7) * 8;
            size_t g = bhoff + (size_t)(kv0 + row) * D_K + c8;
            uint32_t so = (uint32_t)(row * ST + c8) * 2;
            cp16(sb + 0 * FTSZB + so, &Kh[g]);
            cp16(sb + 1 * FTSZB + so, &Kl[g]);
            cp16(sb + 2 * FTSZB + so, &Vh[g]);
            cp16(sb + 3 * FTSZB + so, &Vl[g]);
        }
    };

    float o[8][4];
#pragma unroll
    for (int i = 0; i < 8; i++)
#pragma unroll
        for (int r = 0; r < 4; r++) o[i][r] = 0.f;
    float mA = -1e30f, mB = -1e30f, lA = 0.f, lB = 0.f;

    load_kv(0, 0);
    CP_COMMIT();

    for (int t = 0; t < SEQ / 64; t++) {
        const int cur = t & 1;
        CP_WAIT0();
        __syncthreads();
        if (t < SEQ / 64 - 1) {
            load_kv(cur ^ 1, (t + 1) * 64);
            CP_COMMIT();
        }

        const uint32_t uKh = base + cur * FSTGB;
        const uint32_t uKl = uKh + FTSZB;
        const uint32_t uVh = uKh + 2 * FTSZB;
        const uint32_t uVl = uKh + 3 * FTSZB;

        // ---- S = Q . K^T ----
        float s[8][4];
#pragma unroll
        for (int i = 0; i < 8; i++)
#pragma unroll
            for (int r = 0; r < 4; r++) s[i][r] = 0.f;

        const int brow = lane & 7;
        const int bcol = ((lane & 15) >> 3) * 8;
#pragma unroll
        for (int ks = 0; ks < 4; ks++) {
            uint32_t kh[8][2], kl[8][2];
#pragma unroll
            for (int nt = 0; nt < 8; nt++) {
                uint32_t off = ((nt * 8 + brow) * ST + ks * 16 + bcol) * 2;
                ldsm_x2(kh[nt], uKh + off);
                ldsm_x2(kl[nt], uKl + off);
            }
#pragma unroll
            for (int nt = 0; nt < 8; nt++) mma16816(s[nt], qh[ks], kh[nt]);
#pragma unroll
            for (int nt = 0; nt < 8; nt++) mma16816(s[nt], ql[ks], kh[nt]);
#pragma unroll
            for (int nt = 0; nt < 8; nt++) mma16816(s[nt], qh[ks], kl[nt]);
        }

        // ---- online softmax (log2 domain) ----
        float tA = -1e30f, tB = -1e30f;
#pragma unroll
        for (int nt = 0; nt < 8; nt++) {
            tA = fmaxf(tA, fmaxf(s[nt][0], s[nt][1]));
            tB = fmaxf(tB, fmaxf(s[nt][2], s[nt][3]));
        }
        tA = fmaxf(tA, __shfl_xor_sync(0xffffffff, tA, 1));
        tA = fmaxf(tA, __shfl_xor_sync(0xffffffff, tA, 2));
        tB = fmaxf(tB, __shfl_xor_sync(0xffffffff, tB, 1));
        tB = fmaxf(tB, __shfl_xor_sync(0xffffffff, tB, 2));
        float mnA = fmaxf(mA, tA), mnB = fmaxf(mB, tB);
        float cA = exp2f(mA - mnA), cB = exp2f(mB - mnB);
        lA *= cA; lB *= cB;
#pragma unroll
        for (int nt = 0; nt < 8; nt++) {
            o[nt][0] *= cA; o[nt][1] *= cA;
            o[nt][2] *= cB; o[nt][3] *= cB;
        }
        mA = mnA; mB = mnB;

        // ---- P = exp2(S - m), split hi/lo in registers ----
        uint32_t pAh[8], pAl[8], pBh[8], pBl[8];
#pragma unroll
        for (int nt = 0; nt < 8; nt++) {
            float p0 = exp2f(s[nt][0] - mnA);
            float p1 = exp2f(s[nt][1] - mnA);
            float p2 = exp2f(s[nt][2] - mnB);
            float p3 = exp2f(s[nt][3] - mnB);
            lA += p0 + p1; lB += p2 + p3;
            __half h0 = __float2half_rn(p0), h1 = __float2half_rn(p1);
            __half h2 = __float2half_rn(p2), h3 = __float2half_rn(p3);
            __half2 tt;
            tt.x = h0; tt.y = h1; pAh[nt] = *(uint32_t*)&tt;
            tt.x = h2; tt.y = h3; pBh[nt] = *(uint32_t*)&tt;
            tt.x = __float2half_rn(p0 - __half2float(h0));
            tt.y = __float2half_rn(p1 - __half2float(h1));
            pAl[nt] = *(uint32_t*)&tt;
            tt.x = __float2half_rn(p2 - __half2float(h2));
            tt.y = __float2half_rn(p3 - __half2float(h3));
            pBl[nt] = *(uint32_t*)&tt;
        }

        // ---- O += P . V ----
#pragma unroll
        for (int ks = 0; ks < 4; ks++) {
            uint32_t aPh[4] = { pAh[2 * ks], pBh[2 * ks], pAh[2 * ks + 1], pBh[2 * ks + 1] };
            uint32_t aPl[4] = { pAl[2 * ks], pBl[2 * ks], pAl[2 * ks + 1], pBl[2 * ks + 1] };
            uint32_t vh[8][2], vl[8][2];
#pragma unroll
            for (int ntd = 0; ntd < 8; ntd++) {
                uint32_t off = ((ks * 16 + (lane & 15)) * ST + ntd * 8) * 2;
                ldsm_x2_t(vh[ntd], uVh + off);
                ldsm_x2_t(vl[ntd], uVl + off);
            }
#pragma unroll
            for (int ntd = 0; ntd < 8; ntd++) mma16816(o[ntd], aPh, vh[ntd]);
#pragma unroll
            for (int ntd = 0; ntd < 8; ntd++) mma16816(o[ntd], aPl, vh[ntd]);
#pragma unroll
            for (int ntd = 0; ntd < 8; ntd++) mma16816(o[ntd], aPh, vl[ntd]);
        }
    }

    // ---- finalize ----
    lA += __shfl_xor_sync(0xffffffff, lA, 1);
    lA += __shfl_xor_sync(0xffffffff, lA, 2);
    lB += __shfl_xor_sync(0xffffffff, lB, 1);
    lB += __shfl_xor_sync(0xffffffff, lB, 2);
    float invA = 1.f / lA, invB = 1.f / lB;

    const int b = bh >> 4, h = bh & 15;
    const int rowA = q0 + w * 16 + (lane >> 2);
    const int rowB = rowA + 8;
    const int c2 = 2 * (lane & 3);
#pragma unroll
    for (int ntd = 0; ntd < 8; ntd++) {
        float v0 = o[ntd][0] * invA, v1 = o[ntd][1] * invA;
        float v2 = o[ntd][2] * invB, v3 = o[ntd][3] * invB;
        size_t offA = (size_t)(b * SEQ + rowA) * D_MODEL + h * D_K + ntd * 8 + c2;
        size_t offB = (size_t)(b * SEQ + rowB) * D_MODEL + h * D_K + ntd * 8 + c2;
        __half h0 = __float2half_rn(v0), h1 = __float2half_rn(v1);
        __half h2 = __float2half_rn(v2), h3 = __float2half_rn(v3);
        __half2 t2;
        t2.x = h0; t2.y = h1; *(__half2*)&Oh[offA] = t2;
        t2.x = __float2half_rn(v0 - __half2float(h0));
        t2.y = __float2half_rn(v1 - __half2float(h1));
        *(__half2*)&Ol[offA] = t2;
        t2.x = h2; t2.y = h3; *(__half2*)&Oh[offB] = t2;
        t2.x = __float2half_rn(v2 - __half2float(h2));
        t2.y = __float2half_rn(v3 - __half2float(h3));
        *(__half2*)&Ol[offB] = t2;
    }
}

// ---------------------------------------------------------------------------
// Launch
// ---------------------------------------------------------------------------
extern "C" void kernel_launch(void* const* d_in, const int* in_sizes, int n_in,
                              void* d_out, int out_size)
{
    const float* q   = (const float*)d_in[0];
    const float* k   = (const float*)d_in[1];
    const float* v   = (const float*)d_in[2];
    const float* W_q = (const float*)d_in[3];
    const float* b_q = (const float*)d_in[4];
    const float* W_k = (const float*)d_in[5];
    const float* b_k = (const float*)d_in[6];
    const float* W_v = (const float*)d_in[7];
    const float* b_v = (const float*)d_in[8];
    const float* W_o = (const float*)d_in[9];
    const float* b_o = (const float*)d_in[10];
    float* out = (float*)d_out;

    __half* hf;
    cudaGetSymbolAddress((void**)&hf, g_hf);

    cudaFuncSetAttribute((void*)gemm_qkv, cudaFuncAttributeMaxDynamicSharedMemorySize, GSMEM);
    cudaFuncSetAttribute((void*)gemm_o,   cudaFuncAttributeMaxDynamicSharedMemorySize, GSMEM);
    cudaFuncSetAttribute((void*)flash_mma, cudaFuncAttributeMaxDynamicSharedMemorySize, FSMEM);

    SplitArgs sa;
    sa.src[0] = q;   sa.hi[0] = hf + OFF_IQH; sa.lo[0] = hf + OFF_IQL;
    sa.src[1] = k;   sa.hi[1] = hf + OFF_IKH; sa.lo[1] = hf + OFF_IKL;
    sa.src[2] = v;   sa.hi[2] = hf + OFF_IVH; sa.lo[2] = hf + OFF_IVL;
    sa.src[3] = W_q; sa.hi[3] = hf + OFF_WQH; sa.lo[3] = hf + OFF_WQL;
    sa.src[4] = W_k; sa.hi[4] = hf + OFF_WKH; sa.lo[4] = hf + OFF_WKL;
    sa.src[5] = W_v; sa.hi[5] = hf + OFF_WVH; sa.lo[5] = hf + OFF_WVL;
    sa.src[6] = W_o; sa.hi[6] = hf + OFF_WOH; sa.lo[6] = hf + OFF_WOL;
    split_all<<<16384, 256>>>(sa);

    const float qscale = 0.125f * 1.4426950408889634f;
    GemmQKV gp;
    gp.g[0] = { hf + OFF_IQH, hf + OFF_IQL, hf + OFF_WQH, hf + OFF_WQL, b_q,
                hf + OFF_PQH, hf + OFF_PQL, nullptr, qscale };
    gp.g[1] = { hf + OFF_IKH, hf + OFF_IKL, hf + OFF_WKH, hf + OFF_WKL, b_k,
                hf + OFF_PKH, hf + OFF_PKL, nullptr, 1.0f };
    gp.g[2] = { hf + OFF_IVH, hf + OFF_IVL, hf + OFF_WVH, hf + OFF_WVL, b_v,
                hf + OFF_PVH, hf + OFF_PVL, nullptr, 1.0f };
    dim3 ggrid(D_MODEL / 128, M_TOK / 128, 3);   // (8, 32, 3)
    gemm_qkv<<<ggrid, 256, GSMEM>>>(gp);

    dim3 agrid(SEQ / 64, BSZ * N_HEADS);         // (32, 32)
    flash_mma<<<agrid, 128, FSMEM>>>(hf + OFF_PQH, hf + OFF_PQL,
                                     hf + OFF_PKH, hf + OFF_PKL,
                                     hf + OFF_PVH, hf + OFF_PVL,
                                     hf + OFF_OH, hf + OFF_OL);

    GemmOne go = { hf + OFF_OH, hf + OFF_OL, hf + OFF_WOH, hf + OFF_WOL, b_o,
                   nullptr, nullptr, out, 1.0f };
    dim3 ogrid(D_MODEL / 128, M_TOK / 128, 1);
    gemm_o<<<ogrid, 256, GSMEM>>>(go);
}

// round 10
// speedup vs baseline: 1.4379x; 1.4054x over previous
#include <cuda_runtime.h>
#include <cuda_fp16.h>
#include <cstdint>

#define D_MODEL 1024
#define N_HEADS 16
#define D_K     64
#define SEQ     2048
#define BSZ     2
#define M_TOK   (BSZ * SEQ)   // 4096 tokens

// ---------------------------------------------------------------------------
// fp16 arena (device global: allocation-free rule). 64M halves = 128 MB.
// ---------------------------------------------------------------------------
#define MEG (1048576ULL)
__device__ __half g_hf[64 * MEG];

static const size_t OFF_IQH = 0,        OFF_IQL = 4 * MEG;
static const size_t OFF_IKH = 8 * MEG,  OFF_IKL = 12 * MEG;
static const size_t OFF_IVH = 16 * MEG, OFF_IVL = 20 * MEG;
static const size_t OFF_WQH = 24 * MEG;
static const size_t OFF_WKH = 26 * MEG;
static const size_t OFF_WVH = 28 * MEG;
static const size_t OFF_WOH = 30 * MEG;
static const size_t OFF_PQH = 32 * MEG, OFF_PQL = 36 * MEG;
static const size_t OFF_PKH = 40 * MEG;
static const size_t OFF_PVH = 48 * MEG;
static const size_t OFF_OH = 56 * MEG,  OFF_OL = 60 * MEG;

// ---------------------------------------------------------------------------
// PTX wrappers (baseline PTX — compiles at compute_103)
// ---------------------------------------------------------------------------
__device__ __forceinline__ uint32_t smem_u32(const void* p) {
    uint32_t a;
    asm("{ .reg .u64 t; cvta.to.shared.u64 t, %1; cvt.u32.u64 %0, t; }"
        : "=r"(a) : "l"(p));
    return a;
}
__device__ __forceinline__ void ldsm_x4(uint32_t* r, uint32_t addr) {
    asm volatile("ldmatrix.sync.aligned.m8n8.x4.shared.b16 {%0,%1,%2,%3}, [%4];"
                 : "=r"(r[0]), "=r"(r[1]), "=r"(r[2]), "=r"(r[3]) : "r"(addr));
}
__device__ __forceinline__ void ldsm_x2(uint32_t* r, uint32_t addr) {
    asm volatile("ldmatrix.sync.aligned.m8n8.x2.shared.b16 {%0,%1}, [%2];"
                 : "=r"(r[0]), "=r"(r[1]) : "r"(addr));
}
__device__ __forceinline__ void ldsm_x2_t(uint32_t* r, uint32_t addr) {
    asm volatile("ldmatrix.sync.aligned.m8n8.x2.trans.shared.b16 {%0,%1}, [%2];"
                 : "=r"(r[0]), "=r"(r[1]) : "r"(addr));
}
// fp32-accumulating HMMA
__device__ __forceinline__ void mma16816(float* d, const uint32_t* a, const uint32_t* b) {
    asm volatile(
        "mma.sync.aligned.m16n8k16.row.col.f32.f16.f16.f32 "
        "{%0,%1,%2,%3}, {%4,%5,%6,%7}, {%8,%9}, {%0,%1,%2,%3};"
        : "+f"(d[0]), "+f"(d[1]), "+f"(d[2]), "+f"(d[3])
        : "r"(a[0]), "r"(a[1]), "r"(a[2]), "r"(a[3]), "r"(b[0]), "r"(b[1]));
}
// fp16-accumulating HMMA (for the small lo-pass; values are ~2^-11 of main)
__device__ __forceinline__ void mma16816h(uint32_t* d, const uint32_t* a, const uint32_t* b) {
    asm volatile(
        "mma.sync.aligned.m16n8k16.row.col.f16.f16.f16.f16 "
        "{%0,%1}, {%2,%3,%4,%5}, {%6,%7}, {%0,%1};"
        : "+r"(d[0]), "+r"(d[1])
        : "r"(a[0]), "r"(a[1]), "r"(a[2]), "r"(a[3]), "r"(b[0]), "r"(b[1]));
}
__device__ __forceinline__ void cp16(uint32_t saddr, const void* g) {
    asm volatile("cp.async.cg.shared.global [%0], [%1], 16;"
                 :: "r"(saddr), "l"(g));
}
#define CP_COMMIT() asm volatile("cp.async.commit_group;" ::: "memory")
#define CP_WAIT0()  asm volatile("cp.async.wait_group 0;" ::: "memory")

// ---------------------------------------------------------------------------
// Fused split: all 7 tensors in ONE launch. Weights (segs 3-6) need hi only.
// ---------------------------------------------------------------------------
struct SplitArgs {
    const float* src[7];
    __half* hi[7];
    __half* lo[7];    // nullptr -> skip lo
};

__global__ __launch_bounds__(256)
void split_all(SplitArgs a)
{
    int blk = blockIdx.x;
    int seg, rel;
    if (blk < 12288) { seg = blk >> 12; rel = blk & 4095; }
    else             { seg = 3 + ((blk - 12288) >> 10); rel = (blk - 12288) & 1023; }
    int i = rel * 256 + threadIdx.x;

    float4 v = ((const float4*)a.src[seg])[i];
    __half h0 = __float2half_rn(v.x), h1 = __float2half_rn(v.y);
    __half h2 = __float2half_rn(v.z), h3 = __float2half_rn(v.w);
    __half2 ph0; ph0.x = h0; ph0.y = h1;
    __half2 ph1; ph1.x = h2; ph1.y = h3;
    ((__half2*)a.hi[seg])[i * 2 + 0] = ph0;
    ((__half2*)a.hi[seg])[i * 2 + 1] = ph1;
    if (a.lo[seg]) {
        __half2 pl0; pl0.x = __float2half_rn(v.x - __half2float(h0));
        pl0.y = __float2half_rn(v.y - __half2float(h1));
        __half2 pl1; pl1.x = __float2half_rn(v.z - __half2float(h2));
        pl1.y = __float2half_rn(v.w - __half2float(h3));
        ((__half2*)a.lo[seg])[i * 2 + 0] = pl0;
        ((__half2*)a.lo[seg])[i * 2 + 1] = pl1;
    }
}

// ---------------------------------------------------------------------------
// Tensor-core 2-pass GEMM:  C = (Ahi + Alo) * Bhi  (+bias)*scale
//   pass 1: Ahi*Bhi, fp32 accum.  pass 2: Alo*Bhi, fp16 accum (tiny values).
// CTA 128x128, BK=32, 256 threads, warp tile 64x32, 2-stage cp.async.
// ---------------------------------------------------------------------------
#define SP 40                        // smem row stride in halves (80B = 5x16B)
#define TSZB (128 * SP * 2)          // 10240 bytes per tile
#define STGB (3 * TSZB)              // Ah, Al, Bh   (30720)
#define GSMEM (2 * STGB)             // 61440

struct GemmOne {
    const __half* Ah; const __half* Al;
    const __half* Bh;
    const float* bias;
    __half* Ch; __half* Cl;      // MODE 1 outputs (Cl may be nullptr)
    float* C;                    // MODE 0 output
    float scale;
};
struct GemmQKV { GemmOne g[3]; };

template<int MODE>
__device__ __forceinline__ void gemm_core(const GemmOne& P, int bm, int bn)
{
    extern __shared__ __align__(16) char dsm[];
    const uint32_t base = smem_u32(dsm);
    const int tid  = threadIdx.x;
    const int wid  = tid >> 5;
    const int lane = tid & 31;
    const int wm = (wid >> 2) * 64;
    const int wn = (wid & 3) * 32;

    float    acc [4][4][4];
    uint32_t accx[4][4][2];          // fp16x2 cross-term accumulators
#pragma unroll
    for (int i = 0; i < 4; i++)
#pragma unroll
        for (int j = 0; j < 4; j++) {
#pragma unroll
            for (int r = 0; r < 4; r++) acc[i][j][r] = 0.f;
            accx[i][j][0] = 0u; accx[i][j][1] = 0u;
        }

    const int arow = lane & 15;
    const int acol = (lane >> 4) * 8;
    const int brow = lane & 7;
    const int bcol = ((lane & 15) >> 3) * 8;

    auto load_stage = [&](int stg, int k0) {
        uint32_t sb = base + stg * STGB;
#pragma unroll
        for (int j = 0; j < 2; j++) {
            int c    = tid + j * 256;
            int row  = c >> 2;
            int kcol = (c & 3) * 8;
            size_t ga = (size_t)(bm + row) * D_MODEL + k0 + kcol;
            size_t gb = (size_t)(bn + row) * D_MODEL + k0 + kcol;
            uint32_t so = (uint32_t)(row * SP + kcol) * 2;
            cp16(sb + 0 * TSZB + so, &P.Ah[ga]);
            cp16(sb + 1 * TSZB + so, &P.Al[ga]);
            cp16(sb + 2 * TSZB + so, &P.Bh[gb]);
        }
    };

    load_stage(0, 0);
    CP_COMMIT();

    for (int kc = 0; kc < 32; kc++) {
        const int cur = kc & 1;
        CP_WAIT0();
        __syncthreads();
        if (kc < 31) {
            load_stage(cur ^ 1, (kc + 1) * 32);
            CP_COMMIT();
        }

        const uint32_t uAh = base + cur * STGB;
        const uint32_t uAl = uAh + TSZB;
        const uint32_t uBh = uAh + 2 * TSZB;

#pragma unroll
        for (int ks = 0; ks < 2; ks++) {
            uint32_t ah[4][4], al[4][4], bh[4][2];
#pragma unroll
            for (int mt = 0; mt < 4; mt++) {
                uint32_t off = ((wm + mt * 16 + arow) * SP + ks * 16 + acol) * 2;
                ldsm_x4(ah[mt], uAh + off);
                ldsm_x4(al[mt], uAl + off);
            }
#pragma unroll
            for (int nt = 0; nt < 4; nt++) {
                uint32_t off = ((wn + nt * 8 + brow) * SP + ks * 16 + bcol) * 2;
                ldsm_x2(bh[nt], uBh + off);
            }
#pragma unroll
            for (int mt = 0; mt < 4; mt++)
#pragma unroll
                for (int nt = 0; nt < 4; nt++)
                    mma16816(acc[mt][nt], ah[mt], bh[nt]);
#pragma unroll
            for (int mt = 0; mt < 4; mt++)
#pragma unroll
                for (int nt = 0; nt < 4; nt++)
                    mma16816h(accx[mt][nt], al[mt], bh[nt]);
        }
    }

#pragma unroll
    for (int mt = 0; mt < 4; mt++) {
#pragma unroll
        for (int half = 0; half < 2; half++) {
            int m = bm + wm + mt * 16 + (lane >> 2) + half * 8;
            int b = m >> 11, s = m & 2047;
#pragma unroll
            for (int nt = 0; nt < 4; nt++) {
                int n = bn + wn + nt * 8 + 2 * (lane & 3);
                __half2 cx = *(__half2*)&accx[mt][nt][half];
                float vx = (acc[mt][nt][half * 2 + 0] + __half2float(cx.x) + P.bias[n + 0]) * P.scale;
                float vy = (acc[mt][nt][half * 2 + 1] + __half2float(cx.y) + P.bias[n + 1]) * P.scale;
                if (MODE == 1) {
                    int h = n >> 6, dd = n & 63;
                    size_t co = ((size_t)(b * N_HEADS + h) * SEQ + s) * D_K + dd;
                    __half hx = __float2half_rn(vx), hy = __float2half_rn(vy);
                    __half2 hh; hh.x = hx; hh.y = hy;
                    *(__half2*)&P.Ch[co] = hh;
                    if (P.Cl) {
                        __half2 ll;
                        ll.x = __float2half_rn(vx - __half2float(hx));
                        ll.y = __float2half_rn(vy - __half2float(hy));
                        *(__half2*)&P.Cl[co] = ll;
                    }
                } else {
                    float2 v; v.x = vx; v.y = vy;
                    *(float2*)&P.C[(size_t)m * D_MODEL + n] = v;
                }
            }
        }
    }
}

__global__ __launch_bounds__(256)
void gemm_qkv(GemmQKV P)
{
    gemm_core<1>(P.g[blockIdx.z], blockIdx.y * 128, blockIdx.x * 128);
}

__global__ __launch_bounds__(256)
void gemm_o(GemmOne P)
{
    gemm_core<0>(P, blockIdx.y * 128, blockIdx.x * 128);
}

// ---------------------------------------------------------------------------
// Flash attention, 2-pass split: S = (Qh+Ql).Kh,  O = (Ph+Pl).Vh.
// lo passes use fp16 accumulation, merged per tile.
// 128 threads, 64 q-rows/CTA, KV tiles 64, 2-stage cp.async (Kh,Vh only).
// ---------------------------------------------------------------------------
#define ST 72
#define FTSZB (64 * ST * 2)          // 9216
#define FSTGB (2 * FTSZB)            // Kh, Vh  (18432)
#define FSMEM (2 * FSTGB)            // 36864

__global__ __launch_bounds__(128)
void flash_mma(const __half* __restrict__ Qh, const __half* __restrict__ Ql,
               const __half* __restrict__ Kh, const __half* __restrict__ Vh,
               __half* __restrict__ Oh, __half* __restrict__ Ol)
{
    extern __shared__ __align__(16) char fsm[];
    const uint32_t base = smem_u32(fsm);

    const int bh  = blockIdx.y;
    const int q0  = blockIdx.x * 64;
    const int tid = threadIdx.x;
    const int w   = tid >> 5;
    const int lane = tid & 31;
    const size_t bhoff = (size_t)bh * SEQ * D_K;

    // ---- stage Q in buffer 1, extract A-fragments into registers ----
    {
        __half* sQh = (__half*)(fsm + FSTGB);
        __half* sQl = (__half*)(fsm + FSTGB + FTSZB);
#pragma unroll
        for (int it = 0; it < 4; it++) {
            int idx = tid + it * 128;
            int row = idx >> 3, c8 = (idx & 7) * 8;
            size_t g = bhoff + (size_t)(q0 + row) * D_K + c8;
            *(uint4*)&sQh[row * ST + c8] = *(const uint4*)&Qh[g];
            *(uint4*)&sQl[row * ST + c8] = *(const uint4*)&Ql[g];
        }
    }
    __syncthreads();
    uint32_t qh[4][4], ql[4][4];
    {
        const uint32_t uQh = base + FSTGB, uQl = base + FSTGB + FTSZB;
        const int arow = lane & 15, acol = (lane >> 4) * 8;
#pragma unroll
        for (int ks = 0; ks < 4; ks++) {
            uint32_t off = ((w * 16 + arow) * ST + ks * 16 + acol) * 2;
            ldsm_x4(qh[ks], uQh + off);
            ldsm_x4(ql[ks], uQl + off);
        }
    }
    __syncthreads();

    auto load_kv = [&](int stg, int kv0) {
        uint32_t sb = base + stg * FSTGB;
#pragma unroll
        for (int it = 0; it < 4; it++) {
            int idx = tid + it * 128;
            int row = idx >> 3, c8 = (idx & 7) * 8;
            size_t g = bhoff + (size_t)(kv0 + row) * D_K + c8;
            uint32_t so = (uint32_t)(row * ST + c8) * 2;
            cp16(sb + 0 * FTSZB + so, &Kh[g]);
            cp16(sb + 1 * FTSZB + so, &Vh[g]);
        }
    };

    float o[8][4];
#pragma unroll
    for (int i = 0; i < 8; i++)
#pragma unroll
        for (int r = 0; r < 4; r++) o[i][r] = 0.f;
    float mA = -1e30f, mB = -1e30f, lA = 0.f, lB = 0.f;

    load_kv(0, 0);
    CP_COMMIT();

    for (int t = 0; t < SEQ / 64; t++) {
        const int cur = t & 1;
        CP_WAIT0();
        __syncthreads();
        if (t < SEQ / 64 - 1) {
            load_kv(cur ^ 1, (t + 1) * 64);
            CP_COMMIT();
        }

        const uint32_t uKh = base + cur * FSTGB;
        const uint32_t uVh = uKh + FTSZB;

        // ---- S = (Qh+Ql) . Kh ----
        float s[8][4];
        uint32_t sx[8][2];
#pragma unroll
        for (int i = 0; i < 8; i++) {
#pragma unroll
            for (int r = 0; r < 4; r++) s[i][r] = 0.f;
            sx[i][0] = 0u; sx[i][1] = 0u;
        }

        const int brow = lane & 7;
        const int bcol = ((lane & 15) >> 3) * 8;
#pragma unroll
        for (int ks = 0; ks < 4; ks++) {
            uint32_t kk[8][2];
#pragma unroll
            for (int nt = 0; nt < 8; nt++) {
                uint32_t off = ((nt * 8 + brow) * ST + ks * 16 + bcol) * 2;
                ldsm_x2(kk[nt], uKh + off);
            }
#pragma unroll
            for (int nt = 0; nt < 8; nt++) mma16816(s[nt], qh[ks], kk[nt]);
#pragma unroll
            for (int nt = 0; nt < 8; nt++) mma16816h(sx[nt], ql[ks], kk[nt]);
        }
        // merge lo-pass
#pragma unroll
        for (int nt = 0; nt < 8; nt++) {
            __half2 e0 = *(__half2*)&sx[nt][0];
            __half2 e1 = *(__half2*)&sx[nt][1];
            s[nt][0] += __half2float(e0.x); s[nt][1] += __half2float(e0.y);
            s[nt][2] += __half2float(e1.x); s[nt][3] += __half2float(e1.y);
        }

        // ---- online softmax (log2 domain) ----
        float tA = -1e30f, tB = -1e30f;
#pragma unroll
        for (int nt = 0; nt < 8; nt++) {
            tA = fmaxf(tA, fmaxf(s[nt][0], s[nt][1]));
            tB = fmaxf(tB, fmaxf(s[nt][2], s[nt][3]));
        }
        tA = fmaxf(tA, __shfl_xor_sync(0xffffffff, tA, 1));
        tA = fmaxf(tA, __shfl_xor_sync(0xffffffff, tA, 2));
        tB = fmaxf(tB, __shfl_xor_sync(0xffffffff, tB, 1));
        tB = fmaxf(tB, __shfl_xor_sync(0xffffffff, tB, 2));
        float mnA = fmaxf(mA, tA), mnB = fmaxf(mB, tB);
        float cA = exp2f(mA - mnA), cB = exp2f(mB - mnB);
        lA *= cA; lB *= cB;
#pragma unroll
        for (int nt = 0; nt < 8; nt++) {
            o[nt][0] *= cA; o[nt][1] *= cA;
            o[nt][2] *= cB; o[nt][3] *= cB;
        }
        mA = mnA; mB = mnB;

        // ---- P = exp2(S - m), split hi/lo in registers ----
        uint32_t pAh[8], pAl[8], pBh[8], pBl[8];
#pragma unroll
        for (int nt = 0; nt < 8; nt++) {
            float p0 = exp2f(s[nt][0] - mnA);
            float p1 = exp2f(s[nt][1] - mnA);
            float p2 = exp2f(s[nt][2] - mnB);
            float p3 = exp2f(s[nt][3] - mnB);
            lA += p0 + p1; lB += p2 + p3;
            __half h0 = __float2half_rn(p0), h1 = __float2half_rn(p1);
            __half h2 = __float2half_rn(p2), h3 = __float2half_rn(p3);
            __half2 tt;
            tt.x = h0; tt.y = h1; pAh[nt] = *(uint32_t*)&tt;
            tt.x = h2; tt.y = h3; pBh[nt] = *(uint32_t*)&tt;
            tt.x = __float2half_rn(p0 - __half2float(h0));
            tt.y = __float2half_rn(p1 - __half2float(h1));
            pAl[nt] = *(uint32_t*)&tt;
            tt.x = __float2half_rn(p2 - __half2float(h2));
            tt.y = __float2half_rn(p3 - __half2float(h3));
            pBl[nt] = *(uint32_t*)&tt;
        }

        // ---- O += (Ph+Pl) . Vh ----
        uint32_t ox[8][2];
#pragma unroll
        for (int i = 0; i < 8; i++) { ox[i][0] = 0u; ox[i][1] = 0u; }
#pragma unroll
        for (int ks = 0; ks < 4; ks++) {
            uint32_t aPh[4] = { pAh[2 * ks], pBh[2 * ks], pAh[2 * ks + 1], pBh[2 * ks + 1] };
            uint32_t aPl[4] = { pAl[2 * ks], pBl[2 * ks], pAl[2 * ks + 1], pBl[2 * ks + 1] };
            uint32_t vv[8][2];
#pragma unroll
            for (int ntd = 0; ntd < 8; ntd++) {
                uint32_t off = ((ks * 16 + (lane & 15)) * ST + ntd * 8) * 2;
                ldsm_x2_t(vv[ntd], uVh + off);
            }
#pragma unroll
            for (int ntd = 0; ntd < 8; ntd++) mma16816(o[ntd], aPh, vv[ntd]);
#pragma unroll
            for (int ntd = 0; ntd < 8; ntd++) mma16816h(ox[ntd], aPl, vv[ntd]);
        }
        // merge lo-pass
#pragma unroll
        for (int ntd = 0; ntd < 8; ntd++) {
            __half2 e0 = *(__half2*)&ox[ntd][0];
            __half2 e1 = *(__half2*)&ox[ntd][1];
            o[ntd][0] += __half2float(e0.x); o[ntd][1] += __half2float(e0.y);
            o[ntd][2] += __half2float(e1.x); o[ntd][3] += __half2float(e1.y);
        }
    }

    // ---- finalize ----
    lA += __shfl_xor_sync(0xffffffff, lA, 1);
    lA += __shfl_xor_sync(0xffffffff, lA, 2);
    lB += __shfl_xor_sync(0xffffffff, lB, 1);
    lB += __shfl_xor_sync(0xffffffff, lB, 2);
    float invA = 1.f / lA, invB = 1.f / lB;

    const int b = bh >> 4, h = bh & 15;
    const int rowA = q0 + w * 16 + (lane >> 2);
    const int rowB = rowA + 8;
    const int c2 = 2 * (lane & 3);
#pragma unroll
    for (int ntd = 0; ntd < 8; ntd++) {
        float v0 = o[ntd][0] * invA, v1 = o[ntd][1] * invA;
        float v2 = o[ntd][2] * invB, v3 = o[ntd][3] * invB;
        size_t offA = (size_t)(b * SEQ + rowA) * D_MODEL + h * D_K + ntd * 8 + c2;
        size_t offB = (size_t)(b * SEQ + rowB) * D_MODEL + h * D_K + ntd * 8 + c2;
        __half h0 = __float2half_rn(v0), h1 = __float2half_rn(v1);
        __half h2 = __float2half_rn(v2), h3 = __float2half_rn(v3);
        __half2 t2;
        t2.x = h0; t2.y = h1; *(__half2*)&Oh[offA] = t2;
        t2.x = __float2half_rn(v0 - __half2float(h0));
        t2.y = __float2half_rn(v1 - __half2float(h1));
        *(__half2*)&Ol[offA] = t2;
        t2.x = h2; t2.y = h3; *(__half2*)&Oh[offB] = t2;
        t2.x = __float2half_rn(v2 - __half2float(h2));
        t2.y = __float2half_rn(v3 - __half2float(h3));
        *(__half2*)&Ol[offB] = t2;
    }
}

// ---------------------------------------------------------------------------
// Launch
// ---------------------------------------------------------------------------
extern "C" void kernel_launch(void* const* d_in, const int* in_sizes, int n_in,
                              void* d_out, int out_size)
{
    const float* q   = (const float*)d_in[0];
    const float* k   = (const float*)d_in[1];
    const float* v   = (const float*)d_in[2];
    const float* W_q = (const float*)d_in[3];
    const float* b_q = (const float*)d_in[4];
    const float* W_k = (const float*)d_in[5];
    const float* b_k = (const float*)d_in[6];
    const float* W_v = (const float*)d_in[7];
    const float* b_v = (const float*)d_in[8];
    const float* W_o = (const float*)d_in[9];
    const float* b_o = (const float*)d_in[10];
    float* out = (float*)d_out;

    __half* hf;
    cudaGetSymbolAddress((void**)&hf, g_hf);

    cudaFuncSetAttribute((void*)gemm_qkv, cudaFuncAttributeMaxDynamicSharedMemorySize, GSMEM);
    cudaFuncSetAttribute((void*)gemm_o,   cudaFuncAttributeMaxDynamicSharedMemorySize, GSMEM);
    cudaFuncSetAttribute((void*)flash_mma, cudaFuncAttributeMaxDynamicSharedMemorySize, FSMEM);

    SplitArgs sa;
    sa.src[0] = q;   sa.hi[0] = hf + OFF_IQH; sa.lo[0] = hf + OFF_IQL;
    sa.src[1] = k;   sa.hi[1] = hf + OFF_IKH; sa.lo[1] = hf + OFF_IKL;
    sa.src[2] = v;   sa.hi[2] = hf + OFF_IVH; sa.lo[2] = hf + OFF_IVL;
    sa.src[3] = W_q; sa.hi[3] = hf + OFF_WQH; sa.lo[3] = nullptr;
    sa.src[4] = W_k; sa.hi[4] = hf + OFF_WKH; sa.lo[4] = nullptr;
    sa.src[5] = W_v; sa.hi[5] = hf + OFF_WVH; sa.lo[5] = nullptr;
    sa.src[6] = W_o; sa.hi[6] = hf + OFF_WOH; sa.lo[6] = nullptr;
    split_all<<<16384, 256>>>(sa);

    const float qscale = 0.125f * 1.4426950408889634f;
    GemmQKV gp;
    gp.g[0] = { hf + OFF_IQH, hf + OFF_IQL, hf + OFF_WQH, b_q,
                hf + OFF_PQH, hf + OFF_PQL, nullptr, qscale };
    gp.g[1] = { hf + OFF_IKH, hf + OFF_IKL, hf + OFF_WKH, b_k,
                hf + OFF_PKH, nullptr, nullptr, 1.0f };
    gp.g[2] = { hf + OFF_IVH, hf + OFF_IVL, hf + OFF_WVH, b_v,
                hf + OFF_PVH, nullptr, nullptr, 1.0f };
    dim3 ggrid(D_MODEL / 128, M_TOK / 128, 3);   // (8, 32, 3)
    gemm_qkv<<<ggrid, 256, GSMEM>>>(gp);

    dim3 agrid(SEQ / 64, BSZ * N_HEADS);         // (32, 32)
    flash_mma<<<agrid, 128, FSMEM>>>(hf + OFF_PQH, hf + OFF_PQL,
                                     hf + OFF_PKH, hf + OFF_PVH,
                                     hf + OFF_OH, hf + OFF_OL);

    GemmOne go = { hf + OFF_OH, hf + OFF_OL, hf + OFF_WOH, b_o,
                   nullptr, nullptr, out, 1.0f };
    dim3 ogrid(D_MODEL / 128, M_TOK / 128, 1);
    gemm_o<<<ogrid, 256, GSMEM>>>(go);
}

// round 11
// speedup vs baseline: 1.8992x; 1.3208x over previous
#include <cuda_runtime.h>
#include <cuda_fp16.h>
#include <cstdint>

#define D_MODEL 1024
#define N_HEADS 16
#define D_K     64
#define SEQ     2048
#define BSZ     2
#define M_TOK   (BSZ * SEQ)   // 4096 tokens

// ---------------------------------------------------------------------------
// fp16 arena (device global: allocation-free rule). 64M halves = 128 MB.
// ---------------------------------------------------------------------------
#define MEG (1048576ULL)
__device__ __half g_hf[64 * MEG];

static const size_t OFF_IQH = 0;
static const size_t OFF_IKH = 8 * MEG;
static const size_t OFF_IVH = 16 * MEG, OFF_IVL = 20 * MEG;
static const size_t OFF_WQH = 24 * MEG;
static const size_t OFF_WKH = 26 * MEG;
static const size_t OFF_WVH = 28 * MEG;
static const size_t OFF_WOH = 30 * MEG;
static const size_t OFF_PQH = 32 * MEG;
static const size_t OFF_PKH = 40 * MEG;
static const size_t OFF_PVH = 48 * MEG;
static const size_t OFF_OH = 56 * MEG,  OFF_OL = 60 * MEG;

// ---------------------------------------------------------------------------
// PTX wrappers (baseline PTX — compiles at compute_103)
// ---------------------------------------------------------------------------
__device__ __forceinline__ uint32_t smem_u32(const void* p) {
    uint32_t a;
    asm("{ .reg .u64 t; cvta.to.shared.u64 t, %1; cvt.u32.u64 %0, t; }"
        : "=r"(a) : "l"(p));
    return a;
}
__device__ __forceinline__ void ldsm_x4(uint32_t* r, uint32_t addr) {
    asm volatile("ldmatrix.sync.aligned.m8n8.x4.shared.b16 {%0,%1,%2,%3}, [%4];"
                 : "=r"(r[0]), "=r"(r[1]), "=r"(r[2]), "=r"(r[3]) : "r"(addr));
}
__device__ __forceinline__ void ldsm_x2(uint32_t* r, uint32_t addr) {
    asm volatile("ldmatrix.sync.aligned.m8n8.x2.shared.b16 {%0,%1}, [%2];"
                 : "=r"(r[0]), "=r"(r[1]) : "r"(addr));
}
__device__ __forceinline__ void ldsm_x2_t(uint32_t* r, uint32_t addr) {
    asm volatile("ldmatrix.sync.aligned.m8n8.x2.trans.shared.b16 {%0,%1}, [%2];"
                 : "=r"(r[0]), "=r"(r[1]) : "r"(addr));
}
// fp32-accumulating HMMA
__device__ __forceinline__ void mma16816(float* d, const uint32_t* a, const uint32_t* b) {
    asm volatile(
        "mma.sync.aligned.m16n8k16.row.col.f32.f16.f16.f32 "
        "{%0,%1,%2,%3}, {%4,%5,%6,%7}, {%8,%9}, {%0,%1,%2,%3};"
        : "+f"(d[0]), "+f"(d[1]), "+f"(d[2]), "+f"(d[3])
        : "r"(a[0]), "r"(a[1]), "r"(a[2]), "r"(a[3]), "r"(b[0]), "r"(b[1]));
}
// fp16-accumulating HMMA (lo cross-terms)
__device__ __forceinline__ void mma16816h(uint32_t* d, const uint32_t* a, const uint32_t* b) {
    asm volatile(
        "mma.sync.aligned.m16n8k16.row.col.f16.f16.f16.f16 "
        "{%0,%1}, {%2,%3,%4,%5}, {%6,%7}, {%0,%1};"
        : "+r"(d[0]), "+r"(d[1])
        : "r"(a[0]), "r"(a[1]), "r"(a[2]), "r"(a[3]), "r"(b[0]), "r"(b[1]));
}
__device__ __forceinline__ void cp16(uint32_t saddr, const void* g) {
    asm volatile("cp.async.cg.shared.global [%0], [%1], 16;"
                 :: "r"(saddr), "l"(g));
}
#define CP_COMMIT() asm volatile("cp.async.commit_group;" ::: "memory")
#define CP_WAIT0()  asm volatile("cp.async.wait_group 0;" ::: "memory")

// ---------------------------------------------------------------------------
// Fused split: all 7 tensors in ONE launch (lo only where needed).
// ---------------------------------------------------------------------------
struct SplitArgs {
    const float* src[7];
    __half* hi[7];
    __half* lo[7];    // nullptr -> skip lo
};

__global__ __launch_bounds__(256)
void split_all(SplitArgs a)
{
    int blk = blockIdx.x;
    int seg, rel;
    if (blk < 12288) { seg = blk >> 12; rel = blk & 4095; }
    else             { seg = 3 + ((blk - 12288) >> 10); rel = (blk - 12288) & 1023; }
    int i = rel * 256 + threadIdx.x;

    float4 v = ((const float4*)a.src[seg])[i];
    __half h0 = __float2half_rn(v.x), h1 = __float2half_rn(v.y);
    __half h2 = __float2half_rn(v.z), h3 = __float2half_rn(v.w);
    __half2 ph0; ph0.x = h0; ph0.y = h1;
    __half2 ph1; ph1.x = h2; ph1.y = h3;
    ((__half2*)a.hi[seg])[i * 2 + 0] = ph0;
    ((__half2*)a.hi[seg])[i * 2 + 1] = ph1;
    if (a.lo[seg]) {
        __half2 pl0; pl0.x = __float2half_rn(v.x - __half2float(h0));
        pl0.y = __float2half_rn(v.y - __half2float(h1));
        __half2 pl1; pl1.x = __float2half_rn(v.z - __half2float(h2));
        pl1.y = __float2half_rn(v.w - __half2float(h3));
        ((__half2*)a.lo[seg])[i * 2 + 0] = pl0;
        ((__half2*)a.lo[seg])[i * 2 + 1] = pl1;
    }
}

// ---------------------------------------------------------------------------
// Tensor-core GEMM:  C = (Ahi [+ Alo]) * Bhi  (+bias)*scale
//   pass 1: Ahi*Bhi fp32 accum.  pass 2 (if Al): Alo*Bhi fp16 accum.
// CTA 128x128, BK=32, 256 threads, warp tile 64x32, 2-stage cp.async.
// ---------------------------------------------------------------------------
#define SP 40                        // smem row stride in halves (80B = 5x16B)
#define TSZB (128 * SP * 2)          // 10240 bytes per tile
#define STGB (3 * TSZB)              // Ah, Al, Bh   (30720)
#define GSMEM (2 * STGB)             // 61440

struct GemmOne {
    const __half* Ah; const __half* Al;   // Al == nullptr -> single pass
    const __half* Bh;
    const float* bias;
    __half* Ch; __half* Cl;      // MODE 1 outputs (Cl may be nullptr)
    float* C;                    // MODE 0 output
    float scale;
};
struct GemmQKV { GemmOne g[3]; };

template<int MODE>
__device__ __forceinline__ void gemm_core(const GemmOne& P, int bm, int bn)
{
    extern __shared__ __align__(16) char dsm[];
    const uint32_t base = smem_u32(dsm);
    const int tid  = threadIdx.x;
    const int wid  = tid >> 5;
    const int lane = tid & 31;
    const int wm = (wid >> 2) * 64;
    const int wn = (wid & 3) * 32;
    const bool twopass = (P.Al != nullptr);

    float    acc [4][4][4];
    uint32_t accx[4][4][2];
#pragma unroll
    for (int i = 0; i < 4; i++)
#pragma unroll
        for (int j = 0; j < 4; j++) {
#pragma unroll
            for (int r = 0; r < 4; r++) acc[i][j][r] = 0.f;
            accx[i][j][0] = 0u; accx[i][j][1] = 0u;
        }

    const int arow = lane & 15;
    const int acol = (lane >> 4) * 8;
    const int brow = lane & 7;
    const int bcol = ((lane & 15) >> 3) * 8;

    auto load_stage = [&](int stg, int k0) {
        uint32_t sb = base + stg * STGB;
#pragma unroll
        for (int j = 0; j < 2; j++) {
            int c    = tid + j * 256;
            int row  = c >> 2;
            int kcol = (c & 3) * 8;
            size_t ga = (size_t)(bm + row) * D_MODEL + k0 + kcol;
            size_t gb = (size_t)(bn + row) * D_MODEL + k0 + kcol;
            uint32_t so = (uint32_t)(row * SP + kcol) * 2;
            cp16(sb + 0 * TSZB + so, &P.Ah[ga]);
            if (twopass) cp16(sb + 1 * TSZB + so, &P.Al[ga]);
            cp16(sb + 2 * TSZB + so, &P.Bh[gb]);
        }
    };

    load_stage(0, 0);
    CP_COMMIT();

    for (int kc = 0; kc < 32; kc++) {
        const int cur = kc & 1;
        CP_WAIT0();
        __syncthreads();
        if (kc < 31) {
            load_stage(cur ^ 1, (kc + 1) * 32);
            CP_COMMIT();
        }

        const uint32_t uAh = base + cur * STGB;
        const uint32_t uAl = uAh + TSZB;
        const uint32_t uBh = uAh + 2 * TSZB;

#pragma unroll
        for (int ks = 0; ks < 2; ks++) {
            uint32_t ah[4][4], bh[4][2];
#pragma unroll
            for (int mt = 0; mt < 4; mt++) {
                uint32_t off = ((wm + mt * 16 + arow) * SP + ks * 16 + acol) * 2;
                ldsm_x4(ah[mt], uAh + off);
            }
#pragma unroll
            for (int nt = 0; nt < 4; nt++) {
                uint32_t off = ((wn + nt * 8 + brow) * SP + ks * 16 + bcol) * 2;
                ldsm_x2(bh[nt], uBh + off);
            }
#pragma unroll
            for (int mt = 0; mt < 4; mt++)
#pragma unroll
                for (int nt = 0; nt < 4; nt++)
                    mma16816(acc[mt][nt], ah[mt], bh[nt]);
            if (twopass) {
                uint32_t al[4][4];
#pragma unroll
                for (int mt = 0; mt < 4; mt++) {
                    uint32_t off = ((wm + mt * 16 + arow) * SP + ks * 16 + acol) * 2;
                    ldsm_x4(al[mt], uAl + off);
                }
#pragma unroll
                for (int mt = 0; mt < 4; mt++)
#pragma unroll
                    for (int nt = 0; nt < 4; nt++)
                        mma16816h(accx[mt][nt], al[mt], bh[nt]);
            }
        }
    }

#pragma unroll
    for (int mt = 0; mt < 4; mt++) {
#pragma unroll
        for (int half = 0; half < 2; half++) {
            int m = bm + wm + mt * 16 + (lane >> 2) + half * 8;
            int b = m >> 11, s = m & 2047;
#pragma unroll
            for (int nt = 0; nt < 4; nt++) {
                int n = bn + wn + nt * 8 + 2 * (lane & 3);
                __half2 cx = *(__half2*)&accx[mt][nt][half];
                float vx = (acc[mt][nt][half * 2 + 0] + __half2float(cx.x) + P.bias[n + 0]) * P.scale;
                float vy = (acc[mt][nt][half * 2 + 1] + __half2float(cx.y) + P.bias[n + 1]) * P.scale;
                if (MODE == 1) {
                    int h = n >> 6, dd = n & 63;
                    size_t co = ((size_t)(b * N_HEADS + h) * SEQ + s) * D_K + dd;
                    __half hx = __float2half_rn(vx), hy = __float2half_rn(vy);
                    __half2 hh; hh.x = hx; hh.y = hy;
                    *(__half2*)&P.Ch[co] = hh;
                    if (P.Cl) {
                        __half2 ll;
                        ll.x = __float2half_rn(vx - __half2float(hx));
                        ll.y = __float2half_rn(vy - __half2float(hy));
                        *(__half2*)&P.Cl[co] = ll;
                    }
                } else {
                    float2 v; v.x = vx; v.y = vy;
                    *(float2*)&P.C[(size_t)m * D_MODEL + n] = v;
                }
            }
        }
    }
}

__global__ __launch_bounds__(256)
void gemm_qkv(GemmQKV P)
{
    gemm_core<1>(P.g[blockIdx.z], blockIdx.y * 128, blockIdx.x * 128);
}

__global__ __launch_bounds__(256)
void gemm_o(GemmOne P)
{
    gemm_core<0>(P, blockIdx.y * 128, blockIdx.x * 128);
}

// ---------------------------------------------------------------------------
// Flash attention, pure fp16 operands, fp32 accumulation.
// S = Qh.Kh ; P = exp2(S - m) fp16 ; O += Ph.Vh.
// 128 threads, 64 q-rows/CTA, KV tiles 64, 2-stage cp.async (Kh,Vh).
// ---------------------------------------------------------------------------
#define ST 72
#define FTSZB (64 * ST * 2)          // 9216
#define FSTGB (2 * FTSZB)            // Kh, Vh  (18432)
#define FSMEM (2 * FSTGB)            // 36864

__global__ __launch_bounds__(128)
void flash_mma(const __half* __restrict__ Qh,
               const __half* __restrict__ Kh, const __half* __restrict__ Vh,
               __half* __restrict__ Oh, __half* __restrict__ Ol)
{
    extern __shared__ __align__(16) char fsm[];
    const uint32_t base = smem_u32(fsm);

    const int bh  = blockIdx.y;
    const int q0  = blockIdx.x * 64;
    const int tid = threadIdx.x;
    const int w   = tid >> 5;
    const int lane = tid & 31;
    const size_t bhoff = (size_t)bh * SEQ * D_K;

    // ---- stage Qh in buffer 1, extract A-fragments ----
    {
        __half* sQh = (__half*)(fsm + FSTGB);
#pragma unroll
        for (int it = 0; it < 4; it++) {
            int idx = tid + it * 128;
            int row = idx >> 3, c8 = (idx & 7) * 8;
            size_t g = bhoff + (size_t)(q0 + row) * D_K + c8;
            *(uint4*)&sQh[row * ST + c8] = *(const uint4*)&Qh[g];
        }
    }
    __syncthreads();
    uint32_t qh[4][4];
    {
        const uint32_t uQh = base + FSTGB;
        const int arow = lane & 15, acol = (lane >> 4) * 8;
#pragma unroll
        for (int ks = 0; ks < 4; ks++) {
            uint32_t off = ((w * 16 + arow) * ST + ks * 16 + acol) * 2;
            ldsm_x4(qh[ks], uQh + off);
        }
    }
    __syncthreads();

    auto load_kv = [&](int stg, int kv0) {
        uint32_t sb = base + stg * FSTGB;
#pragma unroll
        for (int it = 0; it < 4; it++) {
            int idx = tid + it * 128;
            int row = idx >> 3, c8 = (idx & 7) * 8;
            size_t g = bhoff + (size_t)(kv0 + row) * D_K + c8;
            uint32_t so = (uint32_t)(row * ST + c8) * 2;
            cp16(sb + 0 * FTSZB + so, &Kh[g]);
            cp16(sb + 1 * FTSZB + so, &Vh[g]);
        }
    };

    float o[8][4];
#pragma unroll
    for (int i = 0; i < 8; i++)
#pragma unroll
        for (int r = 0; r < 4; r++) o[i][r] = 0.f;
    float mA = -1e30f, mB = -1e30f, lA = 0.f, lB = 0.f;

    load_kv(0, 0);
    CP_COMMIT();

    for (int t = 0; t < SEQ / 64; t++) {
        const int cur = t & 1;
        CP_WAIT0();
        __syncthreads();
        if (t < SEQ / 64 - 1) {
            load_kv(cur ^ 1, (t + 1) * 64);
            CP_COMMIT();
        }

        const uint32_t uKh = base + cur * FSTGB;
        const uint32_t uVh = uKh + FTSZB;

        // ---- S = Qh . Kh ----
        float s[8][4];
#pragma unroll
        for (int i = 0; i < 8; i++)
#pragma unroll
            for (int r = 0; r < 4; r++) s[i][r] = 0.f;

        const int brow = lane & 7;
        const int bcol = ((lane & 15) >> 3) * 8;
#pragma unroll
        for (int ks = 0; ks < 4; ks++) {
            uint32_t kk[8][2];
#pragma unroll
            for (int nt = 0; nt < 8; nt++) {
                uint32_t off = ((nt * 8 + brow) * ST + ks * 16 + bcol) * 2;
                ldsm_x2(kk[nt], uKh + off);
            }
#pragma unroll
            for (int nt = 0; nt < 8; nt++) mma16816(s[nt], qh[ks], kk[nt]);
        }

        // ---- online softmax (log2 domain) ----
        float tA = -1e30f, tB = -1e30f;
#pragma unroll
        for (int nt = 0; nt < 8; nt++) {
            tA = fmaxf(tA, fmaxf(s[nt][0], s[nt][1]));
            tB = fmaxf(tB, fmaxf(s[nt][2], s[nt][3]));
        }
        tA = fmaxf(tA, __shfl_xor_sync(0xffffffff, tA, 1));
        tA = fmaxf(tA, __shfl_xor_sync(0xffffffff, tA, 2));
        tB = fmaxf(tB, __shfl_xor_sync(0xffffffff, tB, 1));
        tB = fmaxf(tB, __shfl_xor_sync(0xffffffff, tB, 2));
        float mnA = fmaxf(mA, tA), mnB = fmaxf(mB, tB);
        float cA = exp2f(mA - mnA), cB = exp2f(mB - mnB);
        lA *= cA; lB *= cB;
#pragma unroll
        for (int nt = 0; nt < 8; nt++) {
            o[nt][0] *= cA; o[nt][1] *= cA;
            o[nt][2] *= cB; o[nt][3] *= cB;
        }
        mA = mnA; mB = mnB;

        // ---- P = exp2(S - m) -> fp16 ----
        uint32_t pAh[8], pBh[8];
#pragma unroll
        for (int nt = 0; nt < 8; nt++) {
            float p0 = exp2f(s[nt][0] - mnA);
            float p1 = exp2f(s[nt][1] - mnA);
            float p2 = exp2f(s[nt][2] - mnB);
            float p3 = exp2f(s[nt][3] - mnB);
            lA += p0 + p1; lB += p2 + p3;
            __half2 tt;
            tt.x = __float2half_rn(p0); tt.y = __float2half_rn(p1);
            pAh[nt] = *(uint32_t*)&tt;
            tt.x = __float2half_rn(p2); tt.y = __float2half_rn(p3);
            pBh[nt] = *(uint32_t*)&tt;
        }

        // ---- O += Ph . Vh ----
#pragma unroll
        for (int ks = 0; ks < 4; ks++) {
            uint32_t aPh[4] = { pAh[2 * ks], pBh[2 * ks], pAh[2 * ks + 1], pBh[2 * ks + 1] };
            uint32_t vv[8][2];
#pragma unroll
            for (int ntd = 0; ntd < 8; ntd++) {
                uint32_t off = ((ks * 16 + (lane & 15)) * ST + ntd * 8) * 2;
                ldsm_x2_t(vv[ntd], uVh + off);
            }
#pragma unroll
            for (int ntd = 0; ntd < 8; ntd++) mma16816(o[ntd], aPh, vv[ntd]);
        }
    }

    // ---- finalize: normalize, emit hi/lo concat layout ----
    lA += __shfl_xor_sync(0xffffffff, lA, 1);
    lA += __shfl_xor_sync(0xffffffff, lA, 2);
    lB += __shfl_xor_sync(0xffffffff, lB, 1);
    lB += __shfl_xor_sync(0xffffffff, lB, 2);
    float invA = 1.f / lA, invB = 1.f / lB;

    const int b = bh >> 4, h = bh & 15;
    const int rowA = q0 + w * 16 + (lane >> 2);
    const int rowB = rowA + 8;
    const int c2 = 2 * (lane & 3);
#pragma unroll
    for (int ntd = 0; ntd < 8; ntd++) {
        float v0 = o[ntd][0] * invA, v1 = o[ntd][1] * invA;
        float v2 = o[ntd][2] * invB, v3 = o[ntd][3] * invB;
        size_t offA = (size_t)(b * SEQ + rowA) * D_MODEL + h * D_K + ntd * 8 + c2;
        size_t offB = (size_t)(b * SEQ + rowB) * D_MODEL + h * D_K + ntd * 8 + c2;
        __half h0 = __float2half_rn(v0), h1 = __float2half_rn(v1);
        __half h2 = __float2half_rn(v2), h3 = __float2half_rn(v3);
        __half2 t2;
        t2.x = h0; t2.y = h1; *(__half2*)&Oh[offA] = t2;
        t2.x = __float2half_rn(v0 - __half2float(h0));
        t2.y = __float2half_rn(v1 - __half2float(h1));
        *(__half2*)&Ol[offA] = t2;
        t2.x = h2; t2.y = h3; *(__half2*)&Oh[offB] = t2;
        t2.x = __float2half_rn(v2 - __half2float(h2));
        t2.y = __float2half_rn(v3 - __half2float(h3));
        *(__half2*)&Ol[offB] = t2;
    }
}

// ---------------------------------------------------------------------------
// Launch
// ---------------------------------------------------------------------------
extern "C" void kernel_launch(void* const* d_in, const int* in_sizes, int n_in,
                              void* d_out, int out_size)
{
    const float* q   = (const float*)d_in[0];
    const float* k   = (const float*)d_in[1];
    const float* v   = (const float*)d_in[2];
    const float* W_q = (const float*)d_in[3];
    const float* b_q = (const float*)d_in[4];
    const float* W_k = (const float*)d_in[5];
    const float* b_k = (const float*)d_in[6];
    const float* W_v = (const float*)d_in[7];
    const float* b_v = (const float*)d_in[8];
    const float* W_o = (const float*)d_in[9];
    const float* b_o = (const float*)d_in[10];
    float* out = (float*)d_out;

    __half* hf;
    cudaGetSymbolAddress((void**)&hf, g_hf);

    cudaFuncSetAttribute((void*)gemm_qkv, cudaFuncAttributeMaxDynamicSharedMemorySize, GSMEM);
    cudaFuncSetAttribute((void*)gemm_o,   cudaFuncAttributeMaxDynamicSharedMemorySize, GSMEM);
    cudaFuncSetAttribute((void*)flash_mma, cudaFuncAttributeMaxDynamicSharedMemorySize, FSMEM);

    SplitArgs sa;
    sa.src[0] = q;   sa.hi[0] = hf + OFF_IQH; sa.lo[0] = nullptr;
    sa.src[1] = k;   sa.hi[1] = hf + OFF_IKH; sa.lo[1] = nullptr;
    sa.src[2] = v;   sa.hi[2] = hf + OFF_IVH; sa.lo[2] = hf + OFF_IVL;
    sa.src[3] = W_q; sa.hi[3] = hf + OFF_WQH; sa.lo[3] = nullptr;
    sa.src[4] = W_k; sa.hi[4] = hf + OFF_WKH; sa.lo[4] = nullptr;
    sa.src[5] = W_v; sa.hi[5] = hf + OFF_WVH; sa.lo[5] = nullptr;
    sa.src[6] = W_o; sa.hi[6] = hf + OFF_WOH; sa.lo[6] = nullptr;
    split_all<<<16384, 256>>>(sa);

    const float qscale = 0.125f * 1.4426950408889634f;
    GemmQKV gp;
    // Q, K projections: single-pass (errors attenuated by softmax)
    gp.g[0] = { hf + OFF_IQH, nullptr, hf + OFF_WQH, b_q,
                hf + OFF_PQH, nullptr, nullptr, qscale };
    gp.g[1] = { hf + OFF_IKH, nullptr, hf + OFF_WKH, b_k,
                hf + OFF_PKH, nullptr, nullptr, 1.0f };
    // V projection: two-pass (direct error path)
    gp.g[2] = { hf + OFF_IVH, hf + OFF_IVL, hf + OFF_WVH, b_v,
                hf + OFF_PVH, nullptr, nullptr, 1.0f };
    dim3 ggrid(D_MODEL / 128, M_TOK / 128, 3);   // (8, 32, 3)
    gemm_qkv<<<ggrid, 256, GSMEM>>>(gp);

    dim3 agrid(SEQ / 64, BSZ * N_HEADS);         // (32, 32)
    flash_mma<<<agrid, 128, FSMEM>>>(hf + OFF_PQH,
                                     hf + OFF_PKH, hf + OFF_PVH,
                                     hf + OFF_OH, hf + OFF_OL);

    // O projection: two-pass (direct error path)
    GemmOne go = { hf + OFF_OH, hf + OFF_OL, hf + OFF_WOH, b_o,
                   nullptr, nullptr, out, 1.0f };
    dim3 ogrid(D_MODEL / 128, M_TOK / 128, 1);
    gemm_o<<<ogrid, 256, GSMEM>>>(go);
}

// round 12
// speedup vs baseline: 1.9005x; 1.0007x over previous
#include <cuda_runtime.h>
#include <cuda_fp16.h>
#include <cstdint>

#define D_MODEL 1024
#define N_HEADS 16
#define D_K     64
#define SEQ     2048
#define BSZ     2
#define M_TOK   (BSZ * SEQ)   // 4096 tokens

// ---------------------------------------------------------------------------
// fp16 arena (device global: allocation-free rule).
// ---------------------------------------------------------------------------
#define MEG (1048576ULL)
__device__ __half g_hf[40 * MEG];

static const size_t OFF_IQH = 0;             // [b,s,1024] fp16 inputs
static const size_t OFF_IKH = 4 * MEG;
static const size_t OFF_IVH = 8 * MEG;
static const size_t OFF_WQH = 12 * MEG;      // weights
static const size_t OFF_WKH = 13 * MEG;
static const size_t OFF_WVH = 14 * MEG;
static const size_t OFF_WOH = 15 * MEG;
static const size_t OFF_PQH = 16 * MEG;      // projected [b,h,s,d]
static const size_t OFF_PKH = 20 * MEG;
static const size_t OFF_PVH = 24 * MEG;
static const size_t OFF_OH  = 28 * MEG;      // attn out concat [b,s,h*d]

// ---------------------------------------------------------------------------
// PTX wrappers (baseline PTX — compiles at compute_103)
// ---------------------------------------------------------------------------
__device__ __forceinline__ uint32_t smem_u32(const void* p) {
    uint32_t a;
    asm("{ .reg .u64 t; cvta.to.shared.u64 t, %1; cvt.u32.u64 %0, t; }"
        : "=r"(a) : "l"(p));
    return a;
}
__device__ __forceinline__ void ldsm_x4(uint32_t* r, uint32_t addr) {
    asm volatile("ldmatrix.sync.aligned.m8n8.x4.shared.b16 {%0,%1,%2,%3}, [%4];"
                 : "=r"(r[0]), "=r"(r[1]), "=r"(r[2]), "=r"(r[3]) : "r"(addr));
}
__device__ __forceinline__ void ldsm_x2(uint32_t* r, uint32_t addr) {
    asm volatile("ldmatrix.sync.aligned.m8n8.x2.shared.b16 {%0,%1}, [%2];"
                 : "=r"(r[0]), "=r"(r[1]) : "r"(addr));
}
__device__ __forceinline__ void ldsm_x2_t(uint32_t* r, uint32_t addr) {
    asm volatile("ldmatrix.sync.aligned.m8n8.x2.trans.shared.b16 {%0,%1}, [%2];"
                 : "=r"(r[0]), "=r"(r[1]) : "r"(addr));
}
__device__ __forceinline__ void mma16816(float* d, const uint32_t* a, const uint32_t* b) {
    asm volatile(
        "mma.sync.aligned.m16n8k16.row.col.f32.f16.f16.f32 "
        "{%0,%1,%2,%3}, {%4,%5,%6,%7}, {%8,%9}, {%0,%1,%2,%3};"
        : "+f"(d[0]), "+f"(d[1]), "+f"(d[2]), "+f"(d[3])
        : "r"(a[0]), "r"(a[1]), "r"(a[2]), "r"(a[3]), "r"(b[0]), "r"(b[1]));
}
__device__ __forceinline__ void cp16(uint32_t saddr, const void* g) {
    asm volatile("cp.async.cg.shared.global [%0], [%1], 16;"
                 :: "r"(saddr), "l"(g));
}
#define CP_COMMIT() asm volatile("cp.async.commit_group;" ::: "memory")
#define CP_WAIT0()  asm volatile("cp.async.wait_group 0;" ::: "memory")

// ---------------------------------------------------------------------------
// Fused convert: all 7 tensors fp32 -> fp16 (hi only) in ONE launch.
// ---------------------------------------------------------------------------
struct SplitArgs {
    const float* src[7];
    __half* hi[7];
};

__global__ __launch_bounds__(256)
void split_all(SplitArgs a)
{
    int blk = blockIdx.x;
    int seg, rel;
    if (blk < 12288) { seg = blk >> 12; rel = blk & 4095; }
    else             { seg = 3 + ((blk - 12288) >> 10); rel = (blk - 12288) & 1023; }
    int i = rel * 256 + threadIdx.x;

    float4 v = ((const float4*)a.src[seg])[i];
    __half2 ph0; ph0.x = __float2half_rn(v.x); ph0.y = __float2half_rn(v.y);
    __half2 ph1; ph1.x = __float2half_rn(v.z); ph1.y = __float2half_rn(v.w);
    ((__half2*)a.hi[seg])[i * 2 + 0] = ph0;
    ((__half2*)a.hi[seg])[i * 2 + 1] = ph1;
}

// ---------------------------------------------------------------------------
// Tensor-core fp16 GEMM:  C = A * B^T (+bias)*scale, fp32 accumulation.
// CTA 128x128, BK=32, 256 threads, warp tile 64x32, 2-stage cp.async.
// MODE 0: fp32 out [m,n].  MODE 1: fp16 out, [b,h,s,d] head remap.
// ---------------------------------------------------------------------------
#define SP 40                        // smem row stride in halves (80B = 5x16B)
#define TSZB (128 * SP * 2)          // 10240 bytes per tile
#define STGB (2 * TSZB)              // Ah, Bh   (20480)
#define GSMEM (2 * STGB)             // 40960

struct GemmOne {
    const __half* Ah;
    const __half* Bh;
    const float* bias;
    __half* Ch;                  // MODE 1 output
    float* C;                    // MODE 0 output
    float scale;
};
struct GemmQKV { GemmOne g[3]; };

template<int MODE>
__device__ __forceinline__ void gemm_core(const GemmOne& P, int bm, int bn)
{
    extern __shared__ __align__(16) char dsm[];
    const uint32_t base = smem_u32(dsm);
    const int tid  = threadIdx.x;
    const int wid  = tid >> 5;
    const int lane = tid & 31;
    const int wm = (wid >> 2) * 64;
    const int wn = (wid & 3) * 32;

    float acc[4][4][4];
#pragma unroll
    for (int i = 0; i < 4; i++)
#pragma unroll
        for (int j = 0; j < 4; j++)
#pragma unroll
            for (int r = 0; r < 4; r++) acc[i][j][r] = 0.f;

    const int arow = lane & 15;
    const int acol = (lane >> 4) * 8;
    const int brow = lane & 7;
    const int bcol = ((lane & 15) >> 3) * 8;

    auto load_stage = [&](int stg, int k0) {
        uint32_t sb = base + stg * STGB;
#pragma unroll
        for (int j = 0; j < 2; j++) {
            int c    = tid + j * 256;
            int row  = c >> 2;
            int kcol = (c & 3) * 8;
            size_t ga = (size_t)(bm + row) * D_MODEL + k0 + kcol;
            size_t gb = (size_t)(bn + row) * D_MODEL + k0 + kcol;
            uint32_t so = (uint32_t)(row * SP + kcol) * 2;
            cp16(sb + 0 * TSZB + so, &P.Ah[ga]);
            cp16(sb + 1 * TSZB + so, &P.Bh[gb]);
        }
    };

    load_stage(0, 0);
    CP_COMMIT();

    for (int kc = 0; kc < 32; kc++) {
        const int cur = kc & 1;
        CP_WAIT0();
        __syncthreads();
        if (kc < 31) {
            load_stage(cur ^ 1, (kc + 1) * 32);
            CP_COMMIT();
        }

        const uint32_t uAh = base + cur * STGB;
        const uint32_t uBh = uAh + TSZB;

#pragma unroll
        for (int ks = 0; ks < 2; ks++) {
            uint32_t ah[4][4], bh[4][2];
#pragma unroll
            for (int mt = 0; mt < 4; mt++) {
                uint32_t off = ((wm + mt * 16 + arow) * SP + ks * 16 + acol) * 2;
                ldsm_x4(ah[mt], uAh + off);
            }
#pragma unroll
            for (int nt = 0; nt < 4; nt++) {
                uint32_t off = ((wn + nt * 8 + brow) * SP + ks * 16 + bcol) * 2;
                ldsm_x2(bh[nt], uBh + off);
            }
#pragma unroll
            for (int mt = 0; mt < 4; mt++)
#pragma unroll
                for (int nt = 0; nt < 4; nt++)
                    mma16816(acc[mt][nt], ah[mt], bh[nt]);
        }
    }

#pragma unroll
    for (int mt = 0; mt < 4; mt++) {
#pragma unroll
        for (int half = 0; half < 2; half++) {
            int m = bm + wm + mt * 16 + (lane >> 2) + half * 8;
            int b = m >> 11, s = m & 2047;
#pragma unroll
            for (int nt = 0; nt < 4; nt++) {
                int n = bn + wn + nt * 8 + 2 * (lane & 3);
                float vx = (acc[mt][nt][half * 2 + 0] + P.bias[n + 0]) * P.scale;
                float vy = (acc[mt][nt][half * 2 + 1] + P.bias[n + 1]) * P.scale;
                if (MODE == 1) {
                    int h = n >> 6, dd = n & 63;
                    size_t co = ((size_t)(b * N_HEADS + h) * SEQ + s) * D_K + dd;
                    __half2 hh;
                    hh.x = __float2half_rn(vx); hh.y = __float2half_rn(vy);
                    *(__half2*)&P.Ch[co] = hh;
                } else {
                    float2 v; v.x = vx; v.y = vy;
                    *(float2*)&P.C[(size_t)m * D_MODEL + n] = v;
                }
            }
        }
    }
}

__global__ __launch_bounds__(256)
void gemm_qkv(GemmQKV P)
{
    gemm_core<1>(P.g[blockIdx.z], blockIdx.y * 128, blockIdx.x * 128);
}

__global__ __launch_bounds__(256)
void gemm_o(GemmOne P)
{
    gemm_core<0>(P, blockIdx.y * 128, blockIdx.x * 128);
}

// ---------------------------------------------------------------------------
// Flash attention, fp16 operands, fp32 accumulation.
// S = Qh.Kh ; P = exp2(S - m) fp16 ; O += Ph.Vh.  Output: Oh (fp16 concat).
// 128 threads, 64 q-rows/CTA, KV tiles 64, 2-stage cp.async (Kh,Vh).
// ---------------------------------------------------------------------------
#define ST 72
#define FTSZB (64 * ST * 2)          // 9216
#define FSTGB (2 * FTSZB)            // Kh, Vh  (18432)
#define FSMEM (2 * FSTGB)            // 36864

__global__ __launch_bounds__(128)
void flash_mma(const __half* __restrict__ Qh,
               const __half* __restrict__ Kh, const __half* __restrict__ Vh,
               __half* __restrict__ Oh)
{
    extern __shared__ __align__(16) char fsm[];
    const uint32_t base = smem_u32(fsm);

    const int bh  = blockIdx.y;
    const int q0  = blockIdx.x * 64;
    const int tid = threadIdx.x;
    const int w   = tid >> 5;
    const int lane = tid & 31;
    const size_t bhoff = (size_t)bh * SEQ * D_K;

    // ---- stage Qh in buffer 1, extract A-fragments ----
    {
        __half* sQh = (__half*)(fsm + FSTGB);
#pragma unroll
        for (int it = 0; it < 4; it++) {
            int idx = tid + it * 128;
            int row = idx >> 3, c8 = (idx & 7) * 8;
            size_t g = bhoff + (size_t)(q0 + row) * D_K + c8;
            *(uint4*)&sQh[row * ST + c8] = *(const uint4*)&Qh[g];
        }
    }
    __syncthreads();
    uint32_t qh[4][4];
    {
        const uint32_t uQh = base + FSTGB;
        const int arow = lane & 15, acol = (lane >> 4) * 8;
#pragma unroll
        for (int ks = 0; ks < 4; ks++) {
            uint32_t off = ((w * 16 + arow) * ST + ks * 16 + acol) * 2;
            ldsm_x4(qh[ks], uQh + off);
        }
    }
    __syncthreads();

    auto load_kv = [&](int stg, int kv0) {
        uint32_t sb = base + stg * FSTGB;
#pragma unroll
        for (int it = 0; it < 4; it++) {
            int idx = tid + it * 128;
            int row = idx >> 3, c8 = (idx & 7) * 8;
            size_t g = bhoff + (size_t)(kv0 + row) * D_K + c8;
            uint32_t so = (uint32_t)(row * ST + c8) * 2;
            cp16(sb + 0 * FTSZB + so, &Kh[g]);
            cp16(sb + 1 * FTSZB + so, &Vh[g]);
        }
    };

    float o[8][4];
#pragma unroll
    for (int i = 0; i < 8; i++)
#pragma unroll
        for (int r = 0; r < 4; r++) o[i][r] = 0.f;
    float mA = -1e30f, mB = -1e30f, lA = 0.f, lB = 0.f;

    load_kv(0, 0);
    CP_COMMIT();

    for (int t = 0; t < SEQ / 64; t++) {
        const int cur = t & 1;
        CP_WAIT0();
        __syncthreads();
        if (t < SEQ / 64 - 1) {
            load_kv(cur ^ 1, (t + 1) * 64);
            CP_COMMIT();
        }

        const uint32_t uKh = base + cur * FSTGB;
        const uint32_t uVh = uKh + FTSZB;

        // ---- S = Qh . Kh ----
        float s[8][4];
#pragma unroll
        for (int i = 0; i < 8; i++)
#pragma unroll
            for (int r = 0; r < 4; r++) s[i][r] = 0.f;

        const int brow = lane & 7;
        const int bcol = ((lane & 15) >> 3) * 8;
#pragma unroll
        for (int ks = 0; ks < 4; ks++) {
            uint32_t kk[8][2];
#pragma unroll
            for (int nt = 0; nt < 8; nt++) {
                uint32_t off = ((nt * 8 + brow) * ST + ks * 16 + bcol) * 2;
                ldsm_x2(kk[nt], uKh + off);
            }
#pragma unroll
            for (int nt = 0; nt < 8; nt++) mma16816(s[nt], qh[ks], kk[nt]);
        }

        // ---- online softmax (log2 domain) ----
        float tA = -1e30f, tB = -1e30f;
#pragma unroll
        for (int nt = 0; nt < 8; nt++) {
            tA = fmaxf(tA, fmaxf(s[nt][0], s[nt][1]));
            tB = fmaxf(tB, fmaxf(s[nt][2], s[nt][3]));
        }
        tA = fmaxf(tA, __shfl_xor_sync(0xffffffff, tA, 1));
        tA = fmaxf(tA, __shfl_xor_sync(0xffffffff, tA, 2));
        tB = fmaxf(tB, __shfl_xor_sync(0xffffffff, tB, 1));
        tB = fmaxf(tB, __shfl_xor_sync(0xffffffff, tB, 2));
        float mnA = fmaxf(mA, tA), mnB = fmaxf(mB, tB);
        float cA = exp2f(mA - mnA), cB = exp2f(mB - mnB);
        lA *= cA; lB *= cB;
#pragma unroll
        for (int nt = 0; nt < 8; nt++) {
            o[nt][0] *= cA; o[nt][1] *= cA;
            o[nt][2] *= cB; o[nt][3] *= cB;
        }
        mA = mnA; mB = mnB;

        // ---- P = exp2(S - m) -> fp16 ----
        uint32_t pAh[8], pBh[8];
#pragma unroll
        for (int nt = 0; nt < 8; nt++) {
            float p0 = exp2f(s[nt][0] - mnA);
            float p1 = exp2f(s[nt][1] - mnA);
            float p2 = exp2f(s[nt][2] - mnB);
            float p3 = exp2f(s[nt][3] - mnB);
            lA += p0 + p1; lB += p2 + p3;
            __half2 tt;
            tt.x = __float2half_rn(p0); tt.y = __float2half_rn(p1);
            pAh[nt] = *(uint32_t*)&tt;
            tt.x = __float2half_rn(p2); tt.y = __float2half_rn(p3);
            pBh[nt] = *(uint32_t*)&tt;
        }

        // ---- O += Ph . Vh ----
#pragma unroll
        for (int ks = 0; ks < 4; ks++) {
            uint32_t aPh[4] = { pAh[2 * ks], pBh[2 * ks], pAh[2 * ks + 1], pBh[2 * ks + 1] };
            uint32_t vv[8][2];
#pragma unroll
            for (int ntd = 0; ntd < 8; ntd++) {
                uint32_t off = ((ks * 16 + (lane & 15)) * ST + ntd * 8) * 2;
                ldsm_x2_t(vv[ntd], uVh + off);
            }
#pragma unroll
            for (int ntd = 0; ntd < 8; ntd++) mma16816(o[ntd], aPh, vv[ntd]);
        }
    }

    // ---- finalize: normalize, emit fp16 concat layout ----
    lA += __shfl_xor_sync(0xffffffff, lA, 1);
    lA += __shfl_xor_sync(0xffffffff, lA, 2);
    lB += __shfl_xor_sync(0xffffffff, lB, 1);
    lB += __shfl_xor_sync(0xffffffff, lB, 2);
    float invA = 1.f / lA, invB = 1.f / lB;

    const int b = bh >> 4, h = bh & 15;
    const int rowA = q0 + w * 16 + (lane >> 2);
    const int rowB = rowA + 8;
    const int c2 = 2 * (lane & 3);
#pragma unroll
    for (int ntd = 0; ntd < 8; ntd++) {
        float v0 = o[ntd][0] * invA, v1 = o[ntd][1] * invA;
        float v2 = o[ntd][2] * invB, v3 = o[ntd][3] * invB;
        size_t offA = (size_t)(b * SEQ + rowA) * D_MODEL + h * D_K + ntd * 8 + c2;
        size_t offB = (size_t)(b * SEQ + rowB) * D_MODEL + h * D_K + ntd * 8 + c2;
        __half2 t2;
        t2.x = __float2half_rn(v0); t2.y = __float2half_rn(v1);
        *(__half2*)&Oh[offA] = t2;
        t2.x = __float2half_rn(v2); t2.y = __float2half_rn(v3);
        *(__half2*)&Oh[offB] = t2;
    }
}

// ---------------------------------------------------------------------------
// Launch
// ---------------------------------------------------------------------------
extern "C" void kernel_launch(void* const* d_in, const int* in_sizes, int n_in,
                              void* d_out, int out_size)
{
    const float* q   = (const float*)d_in[0];
    const float* k   = (const float*)d_in[1];
    const float* v   = (const float*)d_in[2];
    const float* W_q = (const float*)d_in[3];
    const float* b_q = (const float*)d_in[4];
    const float* W_k = (const float*)d_in[5];
    const float* b_k = (const float*)d_in[6];
    const float* W_v = (const float*)d_in[7];
    const float* b_v = (const float*)d_in[8];
    const float* W_o = (const float*)d_in[9];
    const float* b_o = (const float*)d_in[10];
    float* out = (float*)d_out;

    __half* hf;
    cudaGetSymbolAddress((void**)&hf, g_hf);

    cudaFuncSetAttribute((void*)gemm_qkv, cudaFuncAttributeMaxDynamicSharedMemorySize, GSMEM);
    cudaFuncSetAttribute((void*)gemm_o,   cudaFuncAttributeMaxDynamicSharedMemorySize, GSMEM);
    cudaFuncSetAttribute((void*)flash_mma, cudaFuncAttributeMaxDynamicSharedMemorySize, FSMEM);

    SplitArgs sa;
    sa.src[0] = q;   sa.hi[0] = hf + OFF_IQH;
    sa.src[1] = k;   sa.hi[1] = hf + OFF_IKH;
    sa.src[2] = v;   sa.hi[2] = hf + OFF_IVH;
    sa.src[3] = W_q; sa.hi[3] = hf + OFF_WQH;
    sa.src[4] = W_k; sa.hi[4] = hf + OFF_WKH;
    sa.src[5] = W_v; sa.hi[5] = hf + OFF_WVH;
    sa.src[6] = W_o; sa.hi[6] = hf + OFF_WOH;
    split_all<<<16384, 256>>>(sa);

    const float qscale = 0.125f * 1.4426950408889634f;
    GemmQKV gp;
    gp.g[0] = { hf + OFF_IQH, hf + OFF_WQH, b_q, hf + OFF_PQH, nullptr, qscale };
    gp.g[1] = { hf + OFF_IKH, hf + OFF_WKH, b_k, hf + OFF_PKH, nullptr, 1.0f };
    gp.g[2] = { hf + OFF_IVH, hf + OFF_WVH, b_v, hf + OFF_PVH, nullptr, 1.0f };
    dim3 ggrid(D_MODEL / 128, M_TOK / 128, 3);   // (8, 32, 3)
    gemm_qkv<<<ggrid, 256, GSMEM>>>(gp);

    dim3 agrid(SEQ / 64, BSZ * N_HEADS);         // (32, 32)
    flash_mma<<<agrid, 128, FSMEM>>>(hf + OFF_PQH,
                                     hf + OFF_PKH, hf + OFF_PVH,
                                     hf + OFF_OH);

    GemmOne go = { hf + OFF_OH, hf + OFF_WOH, b_o, nullptr, out, 1.0f };
    dim3 ogrid(D_MODEL / 128, M_TOK / 128, 1);
    gemm_o<<<ogrid, 256, GSMEM>>>(go);
}

// round 13
// speedup vs baseline: 1.9853x; 1.0447x over previous
#include <cuda_runtime.h>
#include <cuda_fp16.h>
#include <cstdint>

#define D_MODEL 1024
#define N_HEADS 16
#define D_K     64
#define SEQ     2048
#define BSZ     2
#define M_TOK   (BSZ * SEQ)   // 4096 tokens

// ---------------------------------------------------------------------------
// fp16 arena (device global: allocation-free rule).
// ---------------------------------------------------------------------------
#define MEG (1048576ULL)
__device__ __half g_hf[40 * MEG];

static const size_t OFF_IQH = 0;
static const size_t OFF_IKH = 4 * MEG;
static const size_t OFF_IVH = 8 * MEG;
static const size_t OFF_WQH = 12 * MEG;
static const size_t OFF_WKH = 13 * MEG;
static const size_t OFF_WVH = 14 * MEG;
static const size_t OFF_WOH = 15 * MEG;
static const size_t OFF_PQH = 16 * MEG;
static const size_t OFF_PKH = 20 * MEG;
static const size_t OFF_PVH = 24 * MEG;
static const size_t OFF_OH  = 28 * MEG;

// ---------------------------------------------------------------------------
// PTX wrappers (baseline PTX — compiles at compute_103)
// ---------------------------------------------------------------------------
__device__ __forceinline__ uint32_t smem_u32(const void* p) {
    uint32_t a;
    asm("{ .reg .u64 t; cvta.to.shared.u64 t, %1; cvt.u32.u64 %0, t; }"
        : "=r"(a) : "l"(p));
    return a;
}
__device__ __forceinline__ void ldsm_x4(uint32_t* r, uint32_t addr) {
    asm volatile("ldmatrix.sync.aligned.m8n8.x4.shared.b16 {%0,%1,%2,%3}, [%4];"
                 : "=r"(r[0]), "=r"(r[1]), "=r"(r[2]), "=r"(r[3]) : "r"(addr));
}
__device__ __forceinline__ void ldsm_x2(uint32_t* r, uint32_t addr) {
    asm volatile("ldmatrix.sync.aligned.m8n8.x2.shared.b16 {%0,%1}, [%2];"
                 : "=r"(r[0]), "=r"(r[1]) : "r"(addr));
}
__device__ __forceinline__ void ldsm_x2_t(uint32_t* r, uint32_t addr) {
    asm volatile("ldmatrix.sync.aligned.m8n8.x2.trans.shared.b16 {%0,%1}, [%2];"
                 : "=r"(r[0]), "=r"(r[1]) : "r"(addr));
}
__device__ __forceinline__ void mma16816(float* d, const uint32_t* a, const uint32_t* b) {
    asm volatile(
        "mma.sync.aligned.m16n8k16.row.col.f32.f16.f16.f32 "
        "{%0,%1,%2,%3}, {%4,%5,%6,%7}, {%8,%9}, {%0,%1,%2,%3};"
        : "+f"(d[0]), "+f"(d[1]), "+f"(d[2]), "+f"(d[3])
        : "r"(a[0]), "r"(a[1]), "r"(a[2]), "r"(a[3]), "r"(b[0]), "r"(b[1]));
}
__device__ __forceinline__ void cp16(uint32_t saddr, const void* g) {
    asm volatile("cp.async.cg.shared.global [%0], [%1], 16;"
                 :: "r"(saddr), "l"(g));
}
#define CP_COMMIT() asm volatile("cp.async.commit_group;" ::: "memory")
#define CP_WAIT0()  asm volatile("cp.async.wait_group 0;" ::: "memory")

// ---------------------------------------------------------------------------
// Fused convert: all 7 tensors fp32 -> fp16 in ONE launch.
// ---------------------------------------------------------------------------
struct SplitArgs {
    const float* src[7];
    __half* hi[7];
};

__global__ __launch_bounds__(256)
void split_all(SplitArgs a)
{
    int blk = blockIdx.x;
    int seg, rel;
    if (blk < 12288) { seg = blk >> 12; rel = blk & 4095; }
    else             { seg = 3 + ((blk - 12288) >> 10); rel = (blk - 12288) & 1023; }
    int i = rel * 256 + threadIdx.x;

    float4 v = ((const float4*)a.src[seg])[i];
    __half2 ph0; ph0.x = __float2half_rn(v.x); ph0.y = __float2half_rn(v.y);
    __half2 ph1; ph1.x = __float2half_rn(v.z); ph1.y = __float2half_rn(v.w);
    ((__half2*)a.hi[seg])[i * 2 + 0] = ph0;
    ((__half2*)a.hi[seg])[i * 2 + 1] = ph1;
}

// ---------------------------------------------------------------------------
// Tensor-core fp16 GEMM (unchanged from R12): C = A*B^T (+bias)*scale.
// CTA 128x128, BK=32, 256 threads, warp tile 64x32, 2-stage cp.async.
// ---------------------------------------------------------------------------
#define SP 40
#define TSZB (128 * SP * 2)
#define STGB (2 * TSZB)
#define GSMEM (2 * STGB)

struct GemmOne {
    const __half* Ah;
    const __half* Bh;
    const float* bias;
    __half* Ch;
    float* C;
    float scale;
};
struct GemmQKV { GemmOne g[3]; };

template<int MODE>
__device__ __forceinline__ void gemm_core(const GemmOne& P, int bm, int bn)
{
    extern __shared__ __align__(16) char dsm[];
    const uint32_t base = smem_u32(dsm);
    const int tid  = threadIdx.x;
    const int wid  = tid >> 5;
    const int lane = tid & 31;
    const int wm = (wid >> 2) * 64;
    const int wn = (wid & 3) * 32;

    float acc[4][4][4];
#pragma unroll
    for (int i = 0; i < 4; i++)
#pragma unroll
        for (int j = 0; j < 4; j++)
#pragma unroll
            for (int r = 0; r < 4; r++) acc[i][j][r] = 0.f;

    const int arow = lane & 15;
    const int acol = (lane >> 4) * 8;
    const int brow = lane & 7;
    const int bcol = ((lane & 15) >> 3) * 8;

    auto load_stage = [&](int stg, int k0) {
        uint32_t sb = base + stg * STGB;
#pragma unroll
        for (int j = 0; j < 2; j++) {
            int c    = tid + j * 256;
            int row  = c >> 2;
            int kcol = (c & 3) * 8;
            size_t ga = (size_t)(bm + row) * D_MODEL + k0 + kcol;
            size_t gb = (size_t)(bn + row) * D_MODEL + k0 + kcol;
            uint32_t so = (uint32_t)(row * SP + kcol) * 2;
            cp16(sb + 0 * TSZB + so, &P.Ah[ga]);
            cp16(sb + 1 * TSZB + so, &P.Bh[gb]);
        }
    };

    load_stage(0, 0);
    CP_COMMIT();

    for (int kc = 0; kc < 32; kc++) {
        const int cur = kc & 1;
        CP_WAIT0();
        __syncthreads();
        if (kc < 31) {
            load_stage(cur ^ 1, (kc + 1) * 32);
            CP_COMMIT();
        }

        const uint32_t uAh = base + cur * STGB;
        const uint32_t uBh = uAh + TSZB;

#pragma unroll
        for (int ks = 0; ks < 2; ks++) {
            uint32_t ah[4][4], bh[4][2];
#pragma unroll
            for (int mt = 0; mt < 4; mt++) {
                uint32_t off = ((wm + mt * 16 + arow) * SP + ks * 16 + acol) * 2;
                ldsm_x4(ah[mt], uAh + off);
            }
#pragma unroll
            for (int nt = 0; nt < 4; nt++) {
                uint32_t off = ((wn + nt * 8 + brow) * SP + ks * 16 + bcol) * 2;
                ldsm_x2(bh[nt], uBh + off);
            }
#pragma unroll
            for (int mt = 0; mt < 4; mt++)
#pragma unroll
                for (int nt = 0; nt < 4; nt++)
                    mma16816(acc[mt][nt], ah[mt], bh[nt]);
        }
    }

#pragma unroll
    for (int mt = 0; mt < 4; mt++) {
#pragma unroll
        for (int half = 0; half < 2; half++) {
            int m = bm + wm + mt * 16 + (lane >> 2) + half * 8;
            int b = m >> 11, s = m & 2047;
#pragma unroll
            for (int nt = 0; nt < 4; nt++) {
                int n = bn + wn + nt * 8 + 2 * (lane & 3);
                float vx = (acc[mt][nt][half * 2 + 0] + P.bias[n + 0]) * P.scale;
                float vy = (acc[mt][nt][half * 2 + 1] + P.bias[n + 1]) * P.scale;
                if (MODE == 1) {
                    int h = n >> 6, dd = n & 63;
                    size_t co = ((size_t)(b * N_HEADS + h) * SEQ + s) * D_K + dd;
                    __half2 hh;
                    hh.x = __float2half_rn(vx); hh.y = __float2half_rn(vy);
                    *(__half2*)&P.Ch[co] = hh;
                } else {
                    float2 v; v.x = vx; v.y = vy;
                    *(float2*)&P.C[(size_t)m * D_MODEL + n] = v;
                }
            }
        }
    }
}

__global__ __launch_bounds__(256)
void gemm_qkv(GemmQKV P)
{
    gemm_core<1>(P.g[blockIdx.z], blockIdx.y * 128, blockIdx.x * 128);
}

__global__ __launch_bounds__(256)
void gemm_o(GemmOne P)
{
    gemm_core<0>(P, blockIdx.y * 128, blockIdx.x * 128);
}

// ---------------------------------------------------------------------------
// Flash attention, fp16 operands, fp32 accumulation.
// 128 threads (4 warps), 32 q-rows/warp (128/CTA), Q register-resident,
// KV tiles 64, 2-stage cp.async. P converted per-ks inside PV loop.
// ---------------------------------------------------------------------------
#define ST 72
#define FTSZB (64 * ST * 2)          // 9216
#define FSTGB (2 * FTSZB)            // Kh, Vh  (18432)
#define QTSZB (128 * ST * 2)         // 18432
#define QOFF  (2 * FSTGB)            // Q region after KV stages
#define FSMEM (2 * FSTGB + QTSZB)    // 55296

__global__ __launch_bounds__(128)
void flash_mma(const __half* __restrict__ Qh,
               const __half* __restrict__ Kh, const __half* __restrict__ Vh,
               __half* __restrict__ Oh)
{
    extern __shared__ __align__(16) char fsm[];
    const uint32_t base = smem_u32(fsm);

    const int bh  = blockIdx.y;
    const int q0  = blockIdx.x * 128;
    const int tid = threadIdx.x;
    const int w   = tid >> 5;
    const int lane = tid & 31;
    const size_t bhoff = (size_t)bh * SEQ * D_K;

    // ---- stage Q (128 rows), extract register-resident A-fragments ----
    {
        __half* sQh = (__half*)(fsm + QOFF);
#pragma unroll
        for (int it = 0; it < 8; it++) {
            int idx = tid + it * 128;
            int row = idx >> 3, c8 = (idx & 7) * 8;
            size_t g = bhoff + (size_t)(q0 + row) * D_K + c8;
            *(uint4*)&sQh[row * ST + c8] = *(const uint4*)&Qh[g];
        }
    }
    __syncthreads();
    uint32_t qh[2][4][4];
    {
        const uint32_t uQh = base + QOFF;
        const int arow = lane & 15, acol = (lane >> 4) * 8;
#pragma unroll
        for (int mt = 0; mt < 2; mt++)
#pragma unroll
            for (int ks = 0; ks < 4; ks++) {
                uint32_t off = ((w * 32 + mt * 16 + arow) * ST + ks * 16 + acol) * 2;
                ldsm_x4(qh[mt][ks], uQh + off);
            }
    }

    auto load_kv = [&](int stg, int kv0) {
        uint32_t sb = base + stg * FSTGB;
#pragma unroll
        for (int it = 0; it < 4; it++) {
            int idx = tid + it * 128;
            int row = idx >> 3, c8 = (idx & 7) * 8;
            size_t g = bhoff + (size_t)(kv0 + row) * D_K + c8;
            uint32_t so = (uint32_t)(row * ST + c8) * 2;
            cp16(sb + 0 * FTSZB + so, &Kh[g]);
            cp16(sb + 1 * FTSZB + so, &Vh[g]);
        }
    };

    float o[2][8][4];
#pragma unroll
    for (int mt = 0; mt < 2; mt++)
#pragma unroll
        for (int i = 0; i < 8; i++)
#pragma unroll
            for (int r = 0; r < 4; r++) o[mt][i][r] = 0.f;
    float mA[2] = { -1e30f, -1e30f }, mB[2] = { -1e30f, -1e30f };
    float lA[2] = { 0.f, 0.f },       lB[2] = { 0.f, 0.f };

    load_kv(0, 0);
    CP_COMMIT();

    const int brow = lane & 7;
    const int bcol = ((lane & 15) >> 3) * 8;

    for (int t = 0; t < SEQ / 64; t++) {
        const int cur = t & 1;
        CP_WAIT0();
        __syncthreads();
        if (t < SEQ / 64 - 1) {
            load_kv(cur ^ 1, (t + 1) * 64);
            CP_COMMIT();
        }

        const uint32_t uKh = base + cur * FSTGB;
        const uint32_t uVh = uKh + FTSZB;

        // ---- S = Qh . Kh  (32q x 64kv per warp) ----
        float s[2][8][4];
#pragma unroll
        for (int mt = 0; mt < 2; mt++)
#pragma unroll
            for (int i = 0; i < 8; i++)
#pragma unroll
                for (int r = 0; r < 4; r++) s[mt][i][r] = 0.f;

#pragma unroll
        for (int ks = 0; ks < 4; ks++) {
            uint32_t kk[8][2];
#pragma unroll
            for (int nt = 0; nt < 8; nt++) {
                uint32_t off = ((nt * 8 + brow) * ST + ks * 16 + bcol) * 2;
                ldsm_x2(kk[nt], uKh + off);
            }
#pragma unroll
            for (int mt = 0; mt < 2; mt++)
#pragma unroll
                for (int nt = 0; nt < 8; nt++)
                    mma16816(s[mt][nt], qh[mt][ks], kk[nt]);
        }

        // ---- online softmax update (per m-tile) ----
        float mnA[2], mnB[2];
#pragma unroll
        for (int mt = 0; mt < 2; mt++) {
            float tA = -1e30f, tB = -1e30f;
#pragma unroll
            for (int nt = 0; nt < 8; nt++) {
                tA = fmaxf(tA, fmaxf(s[mt][nt][0], s[mt][nt][1]));
                tB = fmaxf(tB, fmaxf(s[mt][nt][2], s[mt][nt][3]));
            }
            tA = fmaxf(tA, __shfl_xor_sync(0xffffffff, tA, 1));
            tA = fmaxf(tA, __shfl_xor_sync(0xffffffff, tA, 2));
            tB = fmaxf(tB, __shfl_xor_sync(0xffffffff, tB, 1));
            tB = fmaxf(tB, __shfl_xor_sync(0xffffffff, tB, 2));
            mnA[mt] = fmaxf(mA[mt], tA);
            mnB[mt] = fmaxf(mB[mt], tB);
            float cA = exp2f(mA[mt] - mnA[mt]);
            float cB = exp2f(mB[mt] - mnB[mt]);
            lA[mt] *= cA; lB[mt] *= cB;
#pragma unroll
            for (int nt = 0; nt < 8; nt++) {
                o[mt][nt][0] *= cA; o[mt][nt][1] *= cA;
                o[mt][nt][2] *= cB; o[mt][nt][3] *= cB;
            }
            mA[mt] = mnA[mt]; mB[mt] = mnB[mt];
        }

        // ---- O += P . Vh, P converted per kv-slice ----
#pragma unroll
        for (int ks = 0; ks < 4; ks++) {
            uint32_t vv[8][2];
#pragma unroll
            for (int ntd = 0; ntd < 8; ntd++) {
                uint32_t off = ((ks * 16 + (lane & 15)) * ST + ntd * 8) * 2;
                ldsm_x2_t(vv[ntd], uVh + off);
            }
            uint32_t aPh[2][4];
#pragma unroll
            for (int mt = 0; mt < 2; mt++) {
#pragma unroll
                for (int h16 = 0; h16 < 2; h16++) {
                    int nt = 2 * ks + h16;
                    float p0 = exp2f(s[mt][nt][0] - mnA[mt]);
                    float p1 = exp2f(s[mt][nt][1] - mnA[mt]);
                    float p2 = exp2f(s[mt][nt][2] - mnB[mt]);
                    float p3 = exp2f(s[mt][nt][3] - mnB[mt]);
                    lA[mt] += p0 + p1; lB[mt] += p2 + p3;
                    __half2 tt;
                    tt.x = __float2half_rn(p0); tt.y = __float2half_rn(p1);
                    aPh[mt][h16 * 2 + 0] = *(uint32_t*)&tt;
                    tt.x = __float2half_rn(p2); tt.y = __float2half_rn(p3);
                    aPh[mt][h16 * 2 + 1] = *(uint32_t*)&tt;
                }
            }
#pragma unroll
            for (int mt = 0; mt < 2; mt++)
#pragma unroll
                for (int ntd = 0; ntd < 8; ntd++)
                    mma16816(o[mt][ntd], aPh[mt], vv[ntd]);
        }
    }

    // ---- finalize ----
    const int b = bh >> 4, h = bh & 15;
    const int c2 = 2 * (lane & 3);
#pragma unroll
    for (int mt = 0; mt < 2; mt++) {
        float la = lA[mt], lb = lB[mt];
        la += __shfl_xor_sync(0xffffffff, la, 1);
        la += __shfl_xor_sync(0xffffffff, la, 2);
        lb += __shfl_xor_sync(0xffffffff, lb, 1);
        lb += __shfl_xor_sync(0xffffffff, lb, 2);
        float invA = 1.f / la, invB = 1.f / lb;
        int rowA = q0 + w * 32 + mt * 16 + (lane >> 2);
        int rowB = rowA + 8;
#pragma unroll
        for (int ntd = 0; ntd < 8; ntd++) {
            float v0 = o[mt][ntd][0] * invA, v1 = o[mt][ntd][1] * invA;
            float v2 = o[mt][ntd][2] * invB, v3 = o[mt][ntd][3] * invB;
            size_t offA = (size_t)(b * SEQ + rowA) * D_MODEL + h * D_K + ntd * 8 + c2;
            size_t offB = (size_t)(b * SEQ + rowB) * D_MODEL + h * D_K + ntd * 8 + c2;
            __half2 t2;
            t2.x = __float2half_rn(v0); t2.y = __float2half_rn(v1);
            *(__half2*)&Oh[offA] = t2;
            t2.x = __float2half_rn(v2); t2.y = __float2half_rn(v3);
            *(__half2*)&Oh[offB] = t2;
        }
    }
}

// ---------------------------------------------------------------------------
// Launch
// ---------------------------------------------------------------------------
extern "C" void kernel_launch(void* const* d_in, const int* in_sizes, int n_in,
                              void* d_out, int out_size)
{
    const float* q   = (const float*)d_in[0];
    const float* k   = (const float*)d_in[1];
    const float* v   = (const float*)d_in[2];
    const float* W_q = (const float*)d_in[3];
    const float* b_q = (const float*)d_in[4];
    const float* W_k = (const float*)d_in[5];
    const float* b_k = (const float*)d_in[6];
    const float* W_v = (const float*)d_in[7];
    const float* b_v = (const float*)d_in[8];
    const float* W_o = (const float*)d_in[9];
    const float* b_o = (const float*)d_in[10];
    float* out = (float*)d_out;

    __half* hf;
    cudaGetSymbolAddress((void**)&hf, g_hf);

    cudaFuncSetAttribute((void*)gemm_qkv, cudaFuncAttributeMaxDynamicSharedMemorySize, GSMEM);
    cudaFuncSetAttribute((void*)gemm_o,   cudaFuncAttributeMaxDynamicSharedMemorySize, GSMEM);
    cudaFuncSetAttribute((void*)flash_mma, cudaFuncAttributeMaxDynamicSharedMemorySize, FSMEM);

    SplitArgs sa;
    sa.src[0] = q;   sa.hi[0] = hf + OFF_IQH;
    sa.src[1] = k;   sa.hi[1] = hf + OFF_IKH;
    sa.src[2] = v;   sa.hi[2] = hf + OFF_IVH;
    sa.src[3] = W_q; sa.hi[3] = hf + OFF_WQH;
    sa.src[4] = W_k; sa.hi[4] = hf + OFF_WKH;
    sa.src[5] = W_v; sa.hi[5] = hf + OFF_WVH;
    sa.src[6] = W_o; sa.hi[6] = hf + OFF_WOH;
    split_all<<<16384, 256>>>(sa);

    const float qscale = 0.125f * 1.4426950408889634f;
    GemmQKV gp;
    gp.g[0] = { hf + OFF_IQH, hf + OFF_WQH, b_q, hf + OFF_PQH, nullptr, qscale };
    gp.g[1] = { hf + OFF_IKH, hf + OFF_WKH, b_k, hf + OFF_PKH, nullptr, 1.0f };
    gp.g[2] = { hf + OFF_IVH, hf + OFF_WVH, b_v, hf + OFF_PVH, nullptr, 1.0f };
    dim3 ggrid(D_MODEL / 128, M_TOK / 128, 3);   // (8, 32, 3)
    gemm_qkv<<<ggrid, 256, GSMEM>>>(gp);

    dim3 agrid(SEQ / 128, BSZ * N_HEADS);        // (16, 32) = 512 CTAs
    flash_mma<<<agrid, 128, FSMEM>>>(hf + OFF_PQH,
                                     hf + OFF_PKH, hf + OFF_PVH,
                                     hf + OFF_OH);

    GemmOne go = { hf + OFF_OH, hf + OFF_WOH, b_o, nullptr, out, 1.0f };
    dim3 ogrid(D_MODEL / 128, M_TOK / 128, 1);
    gemm_o<<<ogrid, 256, GSMEM>>>(go);
}

// round 14
// speedup vs baseline: 1.9944x; 1.0046x over previous
#include <cuda_runtime.h>
#include <cuda_fp16.h>
#include <cstdint>

#define D_MODEL 1024
#define N_HEADS 16
#define D_K     64
#define SEQ     2048
#define BSZ     2
#define M_TOK   (BSZ * SEQ)   // 4096 tokens

// ---------------------------------------------------------------------------
// fp16 arena (device global: allocation-free rule).
// ---------------------------------------------------------------------------
#define MEG (1048576ULL)
__device__ __half g_hf[40 * MEG];

static const size_t OFF_IQH = 0;
static const size_t OFF_IKH = 4 * MEG;
static const size_t OFF_IVH = 8 * MEG;
static const size_t OFF_WQH = 12 * MEG;
static const size_t OFF_WKH = 13 * MEG;
static const size_t OFF_WVH = 14 * MEG;
static const size_t OFF_WOH = 15 * MEG;
static const size_t OFF_PQH = 16 * MEG;
static const size_t OFF_PKH = 20 * MEG;
static const size_t OFF_PVH = 24 * MEG;
static const size_t OFF_OH  = 28 * MEG;

// ---------------------------------------------------------------------------
// PTX wrappers (baseline PTX — compiles at compute_103)
// ---------------------------------------------------------------------------
__device__ __forceinline__ uint32_t smem_u32(const void* p) {
    uint32_t a;
    asm("{ .reg .u64 t; cvta.to.shared.u64 t, %1; cvt.u32.u64 %0, t; }"
        : "=r"(a) : "l"(p));
    return a;
}
__device__ __forceinline__ void ldsm_x4(uint32_t* r, uint32_t addr) {
    asm volatile("ldmatrix.sync.aligned.m8n8.x4.shared.b16 {%0,%1,%2,%3}, [%4];"
                 : "=r"(r[0]), "=r"(r[1]), "=r"(r[2]), "=r"(r[3]) : "r"(addr));
}
__device__ __forceinline__ void ldsm_x2(uint32_t* r, uint32_t addr) {
    asm volatile("ldmatrix.sync.aligned.m8n8.x2.shared.b16 {%0,%1}, [%2];"
                 : "=r"(r[0]), "=r"(r[1]) : "r"(addr));
}
__device__ __forceinline__ void ldsm_x2_t(uint32_t* r, uint32_t addr) {
    asm volatile("ldmatrix.sync.aligned.m8n8.x2.trans.shared.b16 {%0,%1}, [%2];"
                 : "=r"(r[0]), "=r"(r[1]) : "r"(addr));
}
__device__ __forceinline__ void mma16816(float* d, const uint32_t* a, const uint32_t* b) {
    asm volatile(
        "mma.sync.aligned.m16n8k16.row.col.f32.f16.f16.f32 "
        "{%0,%1,%2,%3}, {%4,%5,%6,%7}, {%8,%9}, {%0,%1,%2,%3};"
        : "+f"(d[0]), "+f"(d[1]), "+f"(d[2]), "+f"(d[3])
        : "r"(a[0]), "r"(a[1]), "r"(a[2]), "r"(a[3]), "r"(b[0]), "r"(b[1]));
}
__device__ __forceinline__ void cp16(uint32_t saddr, const void* g) {
    asm volatile("cp.async.cg.shared.global [%0], [%1], 16;"
                 :: "r"(saddr), "l"(g));
}
#define CP_COMMIT() asm volatile("cp.async.commit_group;" ::: "memory")
#define CP_WAIT0()  asm volatile("cp.async.wait_group 0;" ::: "memory")

// ---------------------------------------------------------------------------
// Fused convert: all 7 tensors fp32 -> fp16 in ONE launch.
// ---------------------------------------------------------------------------
struct SplitArgs {
    const float* src[7];
    __half* hi[7];
};

__global__ __launch_bounds__(256)
void split_all(SplitArgs a)
{
    int blk = blockIdx.x;
    int seg, rel;
    if (blk < 12288) { seg = blk >> 12; rel = blk & 4095; }
    else             { seg = 3 + ((blk - 12288) >> 10); rel = (blk - 12288) & 1023; }
    int i = rel * 256 + threadIdx.x;

    float4 v = ((const float4*)a.src[seg])[i];
    __half2 ph0; ph0.x = __float2half_rn(v.x); ph0.y = __float2half_rn(v.y);
    __half2 ph1; ph1.x = __float2half_rn(v.z); ph1.y = __float2half_rn(v.w);
    ((__half2*)a.hi[seg])[i * 2 + 0] = ph0;
    ((__half2*)a.hi[seg])[i * 2 + 1] = ph1;
}

// ---------------------------------------------------------------------------
// Tensor-core fp16 GEMM: C = A*B^T (+bias)*scale, fp32 accumulation.
// CTA 128(M) x 256(N), BK=32, 256 threads, warp grid 2x4, warp tile 64x64.
// Single-pass, 2-stage cp.async.
// ---------------------------------------------------------------------------
#define SP 40                         // smem row stride in halves (80B = 5x16B)
#define A_TSZB (128 * SP * 2)         // 10240
#define B_TSZB (256 * SP * 2)         // 20480
#define STGB (A_TSZB + B_TSZB)        // 30720
#define GSMEM (2 * STGB)              // 61440

struct GemmOne {
    const __half* Ah;
    const __half* Bh;
    const float* bias;
    __half* Ch;
    float* C;
    float scale;
};
struct GemmQKV { GemmOne g[3]; };

template<int MODE>
__device__ __forceinline__ void gemm_core(const GemmOne& P, int bm, int bn)
{
    extern __shared__ __align__(16) char dsm[];
    const uint32_t base = smem_u32(dsm);
    const int tid  = threadIdx.x;
    const int wid  = tid >> 5;
    const int lane = tid & 31;
    const int wm = (wid >> 2) * 64;     // 2 warp rows
    const int wn = (wid & 3) * 64;      // 4 warp cols

    float acc[4][8][4];
#pragma unroll
    for (int i = 0; i < 4; i++)
#pragma unroll
        for (int j = 0; j < 8; j++)
#pragma unroll
            for (int r = 0; r < 4; r++) acc[i][j][r] = 0.f;

    const int arow = lane & 15;
    const int acol = (lane >> 4) * 8;
    const int brow = lane & 7;
    const int bcol = ((lane & 15) >> 3) * 8;

    auto load_stage = [&](int stg, int k0) {
        uint32_t sb = base + stg * STGB;
        // A: 128 rows x 4 chunks = 512 chunks
#pragma unroll
        for (int j = 0; j < 2; j++) {
            int c    = tid + j * 256;
            int row  = c >> 2;
            int kcol = (c & 3) * 8;
            size_t ga = (size_t)(bm + row) * D_MODEL + k0 + kcol;
            uint32_t so = (uint32_t)(row * SP + kcol) * 2;
            cp16(sb + so, &P.Ah[ga]);
        }
        // B: 256 rows x 4 chunks = 1024 chunks
#pragma unroll
        for (int j = 0; j < 4; j++) {
            int c    = tid + j * 256;
            int row  = c >> 2;
            int kcol = (c & 3) * 8;
            size_t gb = (size_t)(bn + row) * D_MODEL + k0 + kcol;
            uint32_t so = (uint32_t)(row * SP + kcol) * 2;
            cp16(sb + A_TSZB + so, &P.Bh[gb]);
        }
    };

    load_stage(0, 0);
    CP_COMMIT();

    for (int kc = 0; kc < 32; kc++) {
        const int cur = kc & 1;
        CP_WAIT0();
        __syncthreads();
        if (kc < 31) {
            load_stage(cur ^ 1, (kc + 1) * 32);
            CP_COMMIT();
        }

        const uint32_t uAh = base + cur * STGB;
        const uint32_t uBh = uAh + A_TSZB;

#pragma unroll
        for (int ks = 0; ks < 2; ks++) {
            uint32_t ah[4][4], bh[8][2];
#pragma unroll
            for (int mt = 0; mt < 4; mt++) {
                uint32_t off = ((wm + mt * 16 + arow) * SP + ks * 16 + acol) * 2;
                ldsm_x4(ah[mt], uAh + off);
            }
#pragma unroll
            for (int nt = 0; nt < 8; nt++) {
                uint32_t off = ((wn + nt * 8 + brow) * SP + ks * 16 + bcol) * 2;
                ldsm_x2(bh[nt], uBh + off);
            }
#pragma unroll
            for (int mt = 0; mt < 4; mt++)
#pragma unroll
                for (int nt = 0; nt < 8; nt++)
                    mma16816(acc[mt][nt], ah[mt], bh[nt]);
        }
    }

#pragma unroll
    for (int mt = 0; mt < 4; mt++) {
#pragma unroll
        for (int half = 0; half < 2; half++) {
            int m = bm + wm + mt * 16 + (lane >> 2) + half * 8;
            int b = m >> 11, s = m & 2047;
#pragma unroll
            for (int nt = 0; nt < 8; nt++) {
                int n = bn + wn + nt * 8 + 2 * (lane & 3);
                float vx = (acc[mt][nt][half * 2 + 0] + P.bias[n + 0]) * P.scale;
                float vy = (acc[mt][nt][half * 2 + 1] + P.bias[n + 1]) * P.scale;
                if (MODE == 1) {
                    int h = n >> 6, dd = n & 63;
                    size_t co = ((size_t)(b * N_HEADS + h) * SEQ + s) * D_K + dd;
                    __half2 hh;
                    hh.x = __float2half_rn(vx); hh.y = __float2half_rn(vy);
                    *(__half2*)&P.Ch[co] = hh;
                } else {
                    float2 v; v.x = vx; v.y = vy;
                    *(float2*)&P.C[(size_t)m * D_MODEL + n] = v;
                }
            }
        }
    }
}

__global__ __launch_bounds__(256)
void gemm_qkv(GemmQKV P)
{
    gemm_core<1>(P.g[blockIdx.z], blockIdx.y * 128, blockIdx.x * 256);
}

__global__ __launch_bounds__(256)
void gemm_o(GemmOne P)
{
    gemm_core<0>(P, blockIdx.y * 128, blockIdx.x * 256);
}

// ---------------------------------------------------------------------------
// Flash attention (unchanged from R13): fp16 operands, fp32 accumulation.
// 128 threads, 32 q-rows/warp (128/CTA), Q register-resident, KV tiles 64.
// ---------------------------------------------------------------------------
#define ST 72
#define FTSZB (64 * ST * 2)          // 9216
#define FSTGB (2 * FTSZB)            // Kh, Vh  (18432)
#define QTSZB (128 * ST * 2)         // 18432
#define QOFF  (2 * FSTGB)
#define FSMEM (2 * FSTGB + QTSZB)    // 55296

__global__ __launch_bounds__(128)
void flash_mma(const __half* __restrict__ Qh,
               const __half* __restrict__ Kh, const __half* __restrict__ Vh,
               __half* __restrict__ Oh)
{
    extern __shared__ __align__(16) char fsm[];
    const uint32_t base = smem_u32(fsm);

    const int bh  = blockIdx.y;
    const int q0  = blockIdx.x * 128;
    const int tid = threadIdx.x;
    const int w   = tid >> 5;
    const int lane = tid & 31;
    const size_t bhoff = (size_t)bh * SEQ * D_K;

    {
        __half* sQh = (__half*)(fsm + QOFF);
#pragma unroll
        for (int it = 0; it < 8; it++) {
            int idx = tid + it * 128;
            int row = idx >> 3, c8 = (idx & 7) * 8;
            size_t g = bhoff + (size_t)(q0 + row) * D_K + c8;
            *(uint4*)&sQh[row * ST + c8] = *(const uint4*)&Qh[g];
        }
    }
    __syncthreads();
    uint32_t qh[2][4][4];
    {
        const uint32_t uQh = base + QOFF;
        const int arow = lane & 15, acol = (lane >> 4) * 8;
#pragma unroll
        for (int mt = 0; mt < 2; mt++)
#pragma unroll
            for (int ks = 0; ks < 4; ks++) {
                uint32_t off = ((w * 32 + mt * 16 + arow) * ST + ks * 16 + acol) * 2;
                ldsm_x4(qh[mt][ks], uQh + off);
            }
    }

    auto load_kv = [&](int stg, int kv0) {
        uint32_t sb = base + stg * FSTGB;
#pragma unroll
        for (int it = 0; it < 4; it++) {
            int idx = tid + it * 128;
            int row = idx >> 3, c8 = (idx & 7) * 8;
            size_t g = bhoff + (size_t)(kv0 + row) * D_K + c8;
            uint32_t so = (uint32_t)(row * ST + c8) * 2;
            cp16(sb + 0 * FTSZB + so, &Kh[g]);
            cp16(sb + 1 * FTSZB + so, &Vh[g]);
        }
    };

    float o[2][8][4];
#pragma unroll
    for (int mt = 0; mt < 2; mt++)
#pragma unroll
        for (int i = 0; i < 8; i++)
#pragma unroll
            for (int r = 0; r < 4; r++) o[mt][i][r] = 0.f;
    float mA[2] = { -1e30f, -1e30f }, mB[2] = { -1e30f, -1e30f };
    float lA[2] = { 0.f, 0.f },       lB[2] = { 0.f, 0.f };

    load_kv(0, 0);
    CP_COMMIT();

    const int brow = lane & 7;
    const int bcol = ((lane & 15) >> 3) * 8;

    for (int t = 0; t < SEQ / 64; t++) {
        const int cur = t & 1;
        CP_WAIT0();
        __syncthreads();
        if (t < SEQ / 64 - 1) {
            load_kv(cur ^ 1, (t + 1) * 64);
            CP_COMMIT();
        }

        const uint32_t uKh = base + cur * FSTGB;
        const uint32_t uVh = uKh + FTSZB;

        float s[2][8][4];
#pragma unroll
        for (int mt = 0; mt < 2; mt++)
#pragma unroll
            for (int i = 0; i < 8; i++)
#pragma unroll
                for (int r = 0; r < 4; r++) s[mt][i][r] = 0.f;

#pragma unroll
        for (int ks = 0; ks < 4; ks++) {
            uint32_t kk[8][2];
#pragma unroll
            for (int nt = 0; nt < 8; nt++) {
                uint32_t off = ((nt * 8 + brow) * ST + ks * 16 + bcol) * 2;
                ldsm_x2(kk[nt], uKh + off);
            }
#pragma unroll
            for (int mt = 0; mt < 2; mt++)
#pragma unroll
                for (int nt = 0; nt < 8; nt++)
                    mma16816(s[mt][nt], qh[mt][ks], kk[nt]);
        }

        float mnA[2], mnB[2];
#pragma unroll
        for (int mt = 0; mt < 2; mt++) {
            float tA = -1e30f, tB = -1e30f;
#pragma unroll
            for (int nt = 0; nt < 8; nt++) {
                tA = fmaxf(tA, fmaxf(s[mt][nt][0], s[mt][nt][1]));
                tB = fmaxf(tB, fmaxf(s[mt][nt][2], s[mt][nt][3]));
            }
            tA = fmaxf(tA, __shfl_xor_sync(0xffffffff, tA, 1));
            tA = fmaxf(tA, __shfl_xor_sync(0xffffffff, tA, 2));
            tB = fmaxf(tB, __shfl_xor_sync(0xffffffff, tB, 1));
            tB = fmaxf(tB, __shfl_xor_sync(0xffffffff, tB, 2));
            mnA[mt] = fmaxf(mA[mt], tA);
            mnB[mt] = fmaxf(mB[mt], tB);
            float cA = exp2f(mA[mt] - mnA[mt]);
            float cB = exp2f(mB[mt] - mnB[mt]);
            lA[mt] *= cA; lB[mt] *= cB;
#pragma unroll
            for (int nt = 0; nt < 8; nt++) {
                o[mt][nt][0] *= cA; o[mt][nt][1] *= cA;
                o[mt][nt][2] *= cB; o[mt][nt][3] *= cB;
            }
            mA[mt] = mnA[mt]; mB[mt] = mnB[mt];
        }

#pragma unroll
        for (int ks = 0; ks < 4; ks++) {
            uint32_t vv[8][2];
#pragma unroll
            for (int ntd = 0; ntd < 8; ntd++) {
                uint32_t off = ((ks * 16 + (lane & 15)) * ST + ntd * 8) * 2;
                ldsm_x2_t(vv[ntd], uVh + off);
            }
            uint32_t aPh[2][4];
#pragma unroll
            for (int mt = 0; mt < 2; mt++) {
#pragma unroll
                for (int h16 = 0; h16 < 2; h16++) {
                    int nt = 2 * ks + h16;
                    float p0 = exp2f(s[mt][nt][0] - mnA[mt]);
                    float p1 = exp2f(s[mt][nt][1] - mnA[mt]);
                    float p2 = exp2f(s[mt][nt][2] - mnB[mt]);
                    float p3 = exp2f(s[mt][nt][3] - mnB[mt]);
                    lA[mt] += p0 + p1; lB[mt] += p2 + p3;
                    __half2 tt;
                    tt.x = __float2half_rn(p0); tt.y = __float2half_rn(p1);
                    aPh[mt][h16 * 2 + 0] = *(uint32_t*)&tt;
                    tt.x = __float2half_rn(p2); tt.y = __float2half_rn(p3);
                    aPh[mt][h16 * 2 + 1] = *(uint32_t*)&tt;
                }
            }
#pragma unroll
            for (int mt = 0; mt < 2; mt++)
#pragma unroll
                for (int ntd = 0; ntd < 8; ntd++)
                    mma16816(o[mt][ntd], aPh[mt], vv[ntd]);
        }
    }

    const int b = bh >> 4, h = bh & 15;
    const int c2 = 2 * (lane & 3);
#pragma unroll
    for (int mt = 0; mt < 2; mt++) {
        float la = lA[mt], lb = lB[mt];
        la += __shfl_xor_sync(0xffffffff, la, 1);
        la += __shfl_xor_sync(0xffffffff, la, 2);
        lb += __shfl_xor_sync(0xffffffff, lb, 1);
        lb += __shfl_xor_sync(0xffffffff, lb, 2);
        float invA = 1.f / la, invB = 1.f / lb;
        int rowA = q0 + w * 32 + mt * 16 + (lane >> 2);
        int rowB = rowA + 8;
#pragma unroll
        for (int ntd = 0; ntd < 8; ntd++) {
            float v0 = o[mt][ntd][0] * invA, v1 = o[mt][ntd][1] * invA;
            float v2 = o[mt][ntd][2] * invB, v3 = o[mt][ntd][3] * invB;
            size_t offA = (size_t)(b * SEQ + rowA) * D_MODEL + h * D_K + ntd * 8 + c2;
            size_t offB = (size_t)(b * SEQ + rowB) * D_MODEL + h * D_K + ntd * 8 + c2;
            __half2 t2;
            t2.x = __float2half_rn(v0); t2.y = __float2half_rn(v1);
            *(__half2*)&Oh[offA] = t2;
            t2.x = __float2half_rn(v2); t2.y = __float2half_rn(v3);
            *(__half2*)&Oh[offB] = t2;
        }
    }
}

// ---------------------------------------------------------------------------
// Launch
// ---------------------------------------------------------------------------
extern "C" void kernel_launch(void* const* d_in, const int* in_sizes, int n_in,
                              void* d_out, int out_size)
{
    const float* q   = (const float*)d_in[0];
    const float* k   = (const float*)d_in[1];
    const float* v   = (const float*)d_in[2];
    const float* W_q = (const float*)d_in[3];
    const float* b_q = (const float*)d_in[4];
    const float* W_k = (const float*)d_in[5];
    const float* b_k = (const float*)d_in[6];
    const float* W_v = (const float*)d_in[7];
    const float* b_v = (const float*)d_in[8];
    const float* W_o = (const float*)d_in[9];
    const float* b_o = (const float*)d_in[10];
    float* out = (float*)d_out;

    __half* hf;
    cudaGetSymbolAddress((void**)&hf, g_hf);

    cudaFuncSetAttribute((void*)gemm_qkv, cudaFuncAttributeMaxDynamicSharedMemorySize, GSMEM);
    cudaFuncSetAttribute((void*)gemm_o,   cudaFuncAttributeMaxDynamicSharedMemorySize, GSMEM);
    cudaFuncSetAttribute((void*)flash_mma, cudaFuncAttributeMaxDynamicSharedMemorySize, FSMEM);

    SplitArgs sa;
    sa.src[0] = q;   sa.hi[0] = hf + OFF_IQH;
    sa.src[1] = k;   sa.hi[1] = hf + OFF_IKH;
    sa.src[2] = v;   sa.hi[2] = hf + OFF_IVH;
    sa.src[3] = W_q; sa.hi[3] = hf + OFF_WQH;
    sa.src[4] = W_k; sa.hi[4] = hf + OFF_WKH;
    sa.src[5] = W_v; sa.hi[5] = hf + OFF_WVH;
    sa.src[6] = W_o; sa.hi[6] = hf + OFF_WOH;
    split_all<<<16384, 256>>>(sa);

    const float qscale = 0.125f * 1.4426950408889634f;
    GemmQKV gp;
    gp.g[0] = { hf + OFF_IQH, hf + OFF_WQH, b_q, hf + OFF_PQH, nullptr, qscale };
    gp.g[1] = { hf + OFF_IKH, hf + OFF_WKH, b_k, hf + OFF_PKH, nullptr, 1.0f };
    gp.g[2] = { hf + OFF_IVH, hf + OFF_WVH, b_v, hf + OFF_PVH, nullptr, 1.0f };
    dim3 ggrid(D_MODEL / 256, M_TOK / 128, 3);   // (4, 32, 3) = 384 CTAs
    gemm_qkv<<<ggrid, 256, GSMEM>>>(gp);

    dim3 agrid(SEQ / 128, BSZ * N_HEADS);        // (16, 32) = 512 CTAs
    flash_mma<<<agrid, 128, FSMEM>>>(hf + OFF_PQH,
                                     hf + OFF_PKH, hf + OFF_PVH,
                                     hf + OFF_OH);

    GemmOne go = { hf + OFF_OH, hf + OFF_WOH, b_o, nullptr, out, 1.0f };
    dim3 ogrid(D_MODEL / 256, M_TOK / 128);      // (4, 32) = 128 CTAs
    gemm_o<<<ogrid, 256, GSMEM>>>(go);
}